// round 6
// baseline (speedup 1.0000x reference)
#include <cuda_runtime.h>
#include <cuda_bf16.h>
#include <math.h>
#include <stdint.h>

#define NTOK 4096
#define DMODEL 1024
#define D3 3072
#define NHEAD 16
#define HDIM 64
#define SEQ 1024
#define NB 4
#define NTILES 8
#define DFF 4096

// ---------------- scratch (device globals) -------------------------------------
__device__ float g_qkv[NTOK * D3];
__device__ float g_xres[NTOK * DMODEL];
__device__ float g_n2[NTOK * DMODEL];
__device__ __nv_bfloat16 g_n1h[NTOK * DMODEL], g_n1l[NTOK * DMODEL];
__device__ __nv_bfloat16 g_attnh[NTOK * DMODEL], g_attnl[NTOK * DMODEL];
__device__ __nv_bfloat16 g_n2h[NTOK * DMODEL], g_n2l[NTOK * DMODEL];
__device__ __nv_bfloat16 g_h_hi[(size_t)NTOK * DFF], g_h_lo[(size_t)NTOK * DFF];
// pre-split weights; up/down transposed to [N][K]
__device__ __nv_bfloat16 g_qkvw_h[D3 * DMODEL], g_qkvw_l[D3 * DMODEL];
__device__ __nv_bfloat16 g_outw_h[DMODEL * DMODEL], g_outw_l[DMODEL * DMODEL];
__device__ __nv_bfloat16 g_upw_h[(size_t)NTILES * DFF * DMODEL];
__device__ __nv_bfloat16 g_upw_l[(size_t)NTILES * DFF * DMODEL];
__device__ __nv_bfloat16 g_dnw_h[(size_t)NTILES * DMODEL * DFF];
__device__ __nv_bfloat16 g_dnw_l[(size_t)NTILES * DMODEL * DFF];
__device__ int g_tile_id[NTOK];
__device__ int g_perm[NTOK];
__device__ int g_cnt[NTILES];
__device__ int g_off[NTILES];
__device__ int g_fill[NTILES];

// ---------------- helpers -------------------------------------------------------
__device__ __forceinline__ uint32_t sptr(const void* p) {
    return (uint32_t)__cvta_generic_to_shared(p);
}
__device__ __forceinline__ uint32_t pack_bf2(__nv_bfloat16 a, __nv_bfloat16 b) {
    return (uint32_t)__bfloat16_as_ushort(a) | ((uint32_t)__bfloat16_as_ushort(b) << 16);
}
__device__ __forceinline__ void split4(float4 v, __nv_bfloat16* hi, __nv_bfloat16* lo) {
    float a[4] = {v.x, v.y, v.z, v.w};
    __nv_bfloat16 h[4], l[4];
#pragma unroll
    for (int i = 0; i < 4; i++) {
        h[i] = __float2bfloat16(a[i]);
        l[i] = __float2bfloat16(a[i] - __bfloat162float(h[i]));
    }
    *(uint32_t*)(hi)     = pack_bf2(h[0], h[1]);
    *(uint32_t*)(hi + 2) = pack_bf2(h[2], h[3]);
    *(uint32_t*)(lo)     = pack_bf2(l[0], l[1]);
    *(uint32_t*)(lo + 2) = pack_bf2(l[2], l[3]);
}
__device__ __forceinline__ void split2_store(__nv_bfloat16* hi, __nv_bfloat16* lo,
                                             float v0, float v1) {
    __nv_bfloat16 h0 = __float2bfloat16(v0), h1 = __float2bfloat16(v1);
    __nv_bfloat16 l0 = __float2bfloat16(v0 - __bfloat162float(h0));
    __nv_bfloat16 l1 = __float2bfloat16(v1 - __bfloat162float(h1));
    *(uint32_t*)hi = pack_bf2(h0, h1);
    *(uint32_t*)lo = pack_bf2(l0, l1);
}
__device__ __forceinline__ void split_pack(float x, float y, uint32_t& hi, uint32_t& lo) {
    __nv_bfloat16 hx = __float2bfloat16(x), hy = __float2bfloat16(y);
    __nv_bfloat16 lx = __float2bfloat16(x - __bfloat162float(hx));
    __nv_bfloat16 ly = __float2bfloat16(y - __bfloat162float(hy));
    hi = pack_bf2(hx, hy);
    lo = pack_bf2(lx, ly);
}
__device__ __forceinline__ void ldsm4(uint32_t* r, uint32_t a) {
    asm volatile("ldmatrix.sync.aligned.m8n8.x4.shared.b16 {%0,%1,%2,%3}, [%4];"
                 : "=r"(r[0]), "=r"(r[1]), "=r"(r[2]), "=r"(r[3]) : "r"(a));
}
__device__ __forceinline__ void ldsm4t(uint32_t* r, uint32_t a) {
    asm volatile("ldmatrix.sync.aligned.m8n8.x4.trans.shared.b16 {%0,%1,%2,%3}, [%4];"
                 : "=r"(r[0]), "=r"(r[1]), "=r"(r[2]), "=r"(r[3]) : "r"(a));
}
__device__ __forceinline__ void mma16816(float* c, const uint32_t* a, const uint32_t* b) {
    asm volatile(
        "mma.sync.aligned.m16n8k16.row.col.f32.bf16.bf16.f32 "
        "{%0,%1,%2,%3}, {%4,%5,%6,%7}, {%8,%9}, {%0,%1,%2,%3};"
        : "+f"(c[0]), "+f"(c[1]), "+f"(c[2]), "+f"(c[3])
        : "r"(a[0]), "r"(a[1]), "r"(a[2]), "r"(a[3]), "r"(b[0]), "r"(b[1]));
}
__device__ __forceinline__ void cpa16(uint32_t s, const void* g) {
    asm volatile("cp.async.cg.shared.global [%0], [%1], 16;" :: "r"(s), "l"(g));
}
#define CP_COMMIT() asm volatile("cp.async.commit_group;" ::: "memory")
#define CP_WAIT2() asm volatile("cp.async.wait_group 2;" ::: "memory")
#define CP_WAIT0() asm volatile("cp.async.wait_group 0;" ::: "memory")

// one 32-wide K step: 3-pass compensated bf16 (both operands K-major, stride 40)
__device__ __forceinline__ void mma_compute(const __nv_bfloat16* As_hi, const __nv_bfloat16* As_lo,
                                            const __nv_bfloat16* Bs_hi, const __nv_bfloat16* Bs_lo,
                                            float (*acc)[4][4], int lane, int wm, int wn) {
#pragma unroll
    for (int s = 0; s < 2; s++) {
        const int ks = s * 16;
        uint32_t ah[4][4], al[4][4], bh[4][2], bl[4][2];
#pragma unroll
        for (int mi = 0; mi < 4; mi++) {
            int row = wm * 64 + mi * 16 + (lane & 15);
            int col = ks + ((lane >> 4) & 1) * 8;
            ldsm4(ah[mi], sptr(As_hi + row * 40 + col));
            ldsm4(al[mi], sptr(As_lo + row * 40 + col));
        }
#pragma unroll
        for (int p = 0; p < 2; p++) {
            uint32_t r[4];
            int n = wn * 32 + p * 16 + ((lane >> 4) & 1) * 8 + (lane & 7);
            int col = ks + ((lane >> 3) & 1) * 8;
            uint32_t adr_h = sptr(Bs_hi + n * 40 + col);
            uint32_t adr_l = sptr(Bs_lo + n * 40 + col);
            ldsm4(r, adr_h);
            bh[2 * p][0] = r[0]; bh[2 * p][1] = r[1];
            bh[2 * p + 1][0] = r[2]; bh[2 * p + 1][1] = r[3];
            ldsm4(r, adr_l);
            bl[2 * p][0] = r[0]; bl[2 * p][1] = r[1];
            bl[2 * p + 1][0] = r[2]; bl[2 * p + 1][1] = r[3];
        }
#pragma unroll
        for (int mi = 0; mi < 4; mi++)
#pragma unroll
            for (int ni = 0; ni < 4; ni++) {
                mma16816(acc[mi][ni], ah[mi], bh[ni]);
                mma16816(acc[mi][ni], ah[mi], bl[ni]);
                mma16816(acc[mi][ni], al[mi], bh[ni]);
            }
    }
}

// ---------------- weight pre-split -----------------------------------------------
__global__ void wsplit(const float* __restrict__ src, __nv_bfloat16* __restrict__ dh,
                       __nv_bfloat16* __restrict__ dl) {
    int i = blockIdx.x * 256 + threadIdx.x;
    float4 v = *(const float4*)(src + (size_t)i * 4);
    split4(v, dh + (size_t)i * 4, dl + (size_t)i * 4);
}
// src [z][R][C] -> dst [z][C][R], split
__global__ void wsplit_t(const float* __restrict__ src, __nv_bfloat16* __restrict__ dh,
                         __nv_bfloat16* __restrict__ dl, int R, int C) {
    __shared__ float tile[32][33];
    const size_t zoff = (size_t)blockIdx.z * R * C;
    const float* s = src + zoff;
    __nv_bfloat16* oh = dh + zoff;
    __nv_bfloat16* ol = dl + zoff;
    int x = blockIdx.x * 32 + threadIdx.x;
    int y0 = blockIdx.y * 32;
#pragma unroll
    for (int i = 0; i < 4; i++)
        tile[threadIdx.y + i * 8][threadIdx.x] = s[(size_t)(y0 + threadIdx.y + i * 8) * C + x];
    __syncthreads();
    int x2 = y0 + threadIdx.x;
    int y2 = blockIdx.x * 32;
#pragma unroll
    for (int i = 0; i < 4; i++) {
        float v = tile[threadIdx.x][threadIdx.y + i * 8];
        __nv_bfloat16 h = __float2bfloat16(v);
        size_t di = (size_t)(y2 + threadIdx.y + i * 8) * R + x2;
        oh[di] = h;
        ol[di] = __float2bfloat16(v - __bfloat162float(h));
    }
}

// ---------------- GEMM: C[M,N] = A[M,K] * W[N,K]^T, pre-split bf16, cp.async ------
// MODE 0: +bias -> fp32 C          MODE 1: +bias +resid -> fp32 C
// MODE 2: gather A rows via perm, +bias, relu -> split Oh/Ol (compact)
// MODE 3: A compact (off+row), +bias +resid, scatter -> fp32 C
// stage (bytes): Ah[128*80] @0, Al @10240, Bh @20480, Bl @30720; 4 stages x 40960
#define GSTG_B 40960
#define GSMEM (4 * GSTG_B)

template <int MODE>
__global__ __launch_bounds__(256, 1) void gemm_cp(
    const __nv_bfloat16* __restrict__ Ah, const __nv_bfloat16* __restrict__ Al,
    const __nv_bfloat16* __restrict__ Wh, const __nv_bfloat16* __restrict__ Wl,
    const float* __restrict__ bias, const float* __restrict__ resid,
    float* __restrict__ C, __nv_bfloat16* __restrict__ Oh, __nv_bfloat16* __restrict__ Ol,
    int N, int K) {
    extern __shared__ __nv_bfloat16 dsm[];
    const int tid = threadIdx.x, lane = tid & 31, w = tid >> 5;
    const int wm = w & 1, wn = w >> 1;
    const int bn = blockIdx.x * 128, bm = blockIdx.y * 128;
    int cnt = 0, off = 0;
    if (MODE >= 2) {
        const int t = blockIdx.z;
        cnt = g_cnt[t];
        if (bm >= cnt) return;
        off = g_off[t];
        Wh += (size_t)t * N * K;
        Wl += (size_t)t * N * K;
        bias += (size_t)t * N;
    }
    const uint32_t sb = sptr(dsm);
    // fill-role precompute: 2 iters, each thread owns (row = id>>2, 16B chunk = id&3)
    size_t abase[2], bbase[2];
    uint32_t sdst[2];
    int chs[2];
#pragma unroll
    for (int i = 0; i < 2; i++) {
        int id = tid + i * 256, r = id >> 2, ch = id & 3;
        chs[i] = ch;
        sdst[i] = (uint32_t)(r * 80 + ch * 16);
        if (MODE <= 1) {
            abase[i] = (size_t)(bm + r) * K;
        } else if (MODE == 2) {
            int gr = bm + r;
            int tok = (gr < cnt) ? g_perm[off + gr] : 0;
            abase[i] = (size_t)tok * K;
        } else {
            int gr = bm + r;
            int rr = (gr < cnt) ? gr : 0;
            abase[i] = (size_t)(off + rr) * K;
        }
        bbase[i] = (size_t)(bn + r) * K;
    }
    const int NC = K >> 5;
    auto fill = [&](int s, int c) {
        const int k0 = c * 32;
        const uint32_t st = sb + s * GSTG_B;
#pragma unroll
        for (int i = 0; i < 2; i++) {
            int ke = k0 + chs[i] * 8;
            cpa16(st + sdst[i],         Ah + abase[i] + ke);
            cpa16(st + 10240 + sdst[i], Al + abase[i] + ke);
            cpa16(st + 20480 + sdst[i], Wh + bbase[i] + ke);
            cpa16(st + 30720 + sdst[i], Wl + bbase[i] + ke);
        }
        CP_COMMIT();
    };
    fill(0, 0);
    fill(1, 1);
    fill(2, 2);
    float acc[4][4][4] = {};
    for (int c = 0; c < NC; c++) {
        if (c + 3 < NC) CP_WAIT2(); else CP_WAIT0();
        __syncthreads();
        if (c + 3 < NC) fill((c + 3) & 3, c + 3);
        const __nv_bfloat16* b0 = dsm + (c & 3) * (GSTG_B / 2);
        mma_compute(b0, b0 + 5120, b0 + 10240, b0 + 15360, acc, lane, wm, wn);
    }
    // ---- epilogue
#pragma unroll
    for (int mi = 0; mi < 4; mi++) {
        int r0 = bm + wm * 64 + mi * 16 + (lane >> 2);
#pragma unroll
        for (int ni = 0; ni < 4; ni++) {
            int cn = bn + wn * 32 + ni * 8 + (lane & 3) * 2;
            float2 bs = *(const float2*)(bias + cn);
            if (MODE <= 1) {
                float2 o0 = make_float2(acc[mi][ni][0] + bs.x, acc[mi][ni][1] + bs.y);
                float2 o1 = make_float2(acc[mi][ni][2] + bs.x, acc[mi][ni][3] + bs.y);
                if (MODE == 1) {
                    float2 ra = *(const float2*)(resid + (size_t)r0 * N + cn);
                    float2 rb = *(const float2*)(resid + (size_t)(r0 + 8) * N + cn);
                    o0.x += ra.x; o0.y += ra.y; o1.x += rb.x; o1.y += rb.y;
                }
                *(float2*)(C + (size_t)r0 * N + cn) = o0;
                *(float2*)(C + (size_t)(r0 + 8) * N + cn) = o1;
            } else if (MODE == 2) {
                int la = r0;  // absolute tile row (bm-based)
                if (la < cnt) {
                    float v0 = fmaxf(acc[mi][ni][0] + bs.x, 0.f);
                    float v1 = fmaxf(acc[mi][ni][1] + bs.y, 0.f);
                    split2_store(Oh + (size_t)(off + la) * N + cn,
                                 Ol + (size_t)(off + la) * N + cn, v0, v1);
                }
                if (la + 8 < cnt) {
                    float v2 = fmaxf(acc[mi][ni][2] + bs.x, 0.f);
                    float v3 = fmaxf(acc[mi][ni][3] + bs.y, 0.f);
                    split2_store(Oh + (size_t)(off + la + 8) * N + cn,
                                 Ol + (size_t)(off + la + 8) * N + cn, v2, v3);
                }
            } else {  // MODE 3
                int la = r0;
                if (la < cnt) {
                    int tok = g_perm[off + la];
                    float2 xr = *(const float2*)(resid + (size_t)tok * N + cn);
                    *(float2*)(C + (size_t)tok * N + cn) =
                        make_float2(acc[mi][ni][0] + bs.x + xr.x, acc[mi][ni][1] + bs.y + xr.y);
                }
                if (la + 8 < cnt) {
                    int tok = g_perm[off + la + 8];
                    float2 xr = *(const float2*)(resid + (size_t)tok * N + cn);
                    *(float2*)(C + (size_t)tok * N + cn) =
                        make_float2(acc[mi][ni][2] + bs.x + xr.x, acc[mi][ni][3] + bs.y + xr.y);
                }
            }
        }
    }
}

// ---------------- layernorm with split output -------------------------------------
template <bool FP32OUT>
__global__ void ln_split(const float* __restrict__ x, const float* __restrict__ g,
                         const float* __restrict__ bb, float* __restrict__ y,
                         __nv_bfloat16* __restrict__ yh, __nv_bfloat16* __restrict__ yl) {
    int t = blockIdx.x;
    const float* xr = x + (size_t)t * DMODEL;
    int d = threadIdx.x * 4;
    float4 v = *(const float4*)(xr + d);
    float s = v.x + v.y + v.z + v.w;
    float s2 = v.x * v.x + v.y * v.y + v.z * v.z + v.w * v.w;
#pragma unroll
    for (int o = 16; o; o >>= 1) {
        s += __shfl_xor_sync(0xffffffffu, s, o);
        s2 += __shfl_xor_sync(0xffffffffu, s2, o);
    }
    __shared__ float rs[8], rq[8];
    if ((threadIdx.x & 31) == 0) { rs[threadIdx.x >> 5] = s; rq[threadIdx.x >> 5] = s2; }
    __syncthreads();
    __shared__ float smean, srstd;
    if (threadIdx.x == 0) {
        float a = 0.f, b2 = 0.f;
#pragma unroll
        for (int i = 0; i < 8; i++) { a += rs[i]; b2 += rq[i]; }
        float mean = a * (1.f / DMODEL);
        float var = b2 * (1.f / DMODEL) - mean * mean;
        smean = mean; srstd = rsqrtf(var + 1e-5f);
    }
    __syncthreads();
    float mean = smean, rstd = srstd;
    float4 gv = *(const float4*)(g + d);
    float4 bv = *(const float4*)(bb + d);
    float4 o;
    o.x = (v.x - mean) * rstd * gv.x + bv.x;
    o.y = (v.y - mean) * rstd * gv.y + bv.y;
    o.z = (v.z - mean) * rstd * gv.z + bv.z;
    o.w = (v.w - mean) * rstd * gv.w + bv.w;
    if (FP32OUT) *(float4*)(y + (size_t)t * DMODEL + d) = o;
    split4(o, yh + (size_t)t * DMODEL + d, yl + (size_t)t * DMODEL + d);
}

// ---------------- MMA flash attention (split output) ------------------------------
__global__ __launch_bounds__(128) void attn_mma(const float* __restrict__ qkv,
                                                __nv_bfloat16* __restrict__ oh,
                                                __nv_bfloat16* __restrict__ ol) {
    extern __shared__ __nv_bfloat16 asm_[];
    __nv_bfloat16* Qh = asm_;
    __nv_bfloat16* Ql = asm_ + 4608;
    __nv_bfloat16* Kh = asm_ + 9216;
    __nv_bfloat16* Kl = asm_ + 13824;
    __nv_bfloat16* Vh = asm_ + 18432;
    __nv_bfloat16* Vl = asm_ + 23040;

    const int qt = blockIdx.x, h = blockIdx.y, b = blockIdx.z;
    const int tid = threadIdx.x, lane = tid & 31, wid = tid >> 5;
    const int tok0 = b * SEQ + qt * 64;
    const int wq = wid * 16;

#pragma unroll
    for (int i = 0; i < 8; i++) {
        int idx = i * 128 + tid;
        int row = idx >> 4, col = (idx & 15) * 4;
        float4 v = *(const float4*)(qkv + (size_t)(tok0 + row) * D3 + h * HDIM + col);
        v.x *= 0.125f; v.y *= 0.125f; v.z *= 0.125f; v.w *= 0.125f;
        split4(v, Qh + row * 72 + col, Ql + row * 72 + col);
    }

    float m_[2] = {-1e30f, -1e30f}, l_[2] = {0.f, 0.f};
    float O[8][4] = {};

    for (int kt = 0; kt < 16; kt++) {
        int kb = b * SEQ + kt * 64;
        __syncthreads();
#pragma unroll
        for (int i = 0; i < 8; i++) {
            int idx = i * 128 + tid;
            int row = idx >> 4, col = (idx & 15) * 4;
            const float* base = qkv + (size_t)(kb + row) * D3 + h * HDIM + col;
            float4 kv = *(const float4*)(base + DMODEL);
            split4(kv, Kh + row * 72 + col, Kl + row * 72 + col);
            float4 vv = *(const float4*)(base + 2 * DMODEL);
            split4(vv, Vh + row * 72 + col, Vl + row * 72 + col);
        }
        __syncthreads();

        float S[8][4] = {};
#pragma unroll
        for (int ks = 0; ks < 4; ks++) {
            uint32_t qh[4], ql[4], kh[8][2], kl[8][2];
            {
                int row = wq + (lane & 15);
                int col = ks * 16 + ((lane >> 4) & 1) * 8;
                ldsm4(qh, sptr(Qh + row * 72 + col));
                ldsm4(ql, sptr(Ql + row * 72 + col));
            }
#pragma unroll
            for (int p = 0; p < 4; p++) {
                uint32_t r[4];
                int n = p * 16 + ((lane >> 4) & 1) * 8 + (lane & 7);
                int col = ks * 16 + ((lane >> 3) & 1) * 8;
                ldsm4(r, sptr(Kh + n * 72 + col));
                kh[2 * p][0] = r[0]; kh[2 * p][1] = r[1];
                kh[2 * p + 1][0] = r[2]; kh[2 * p + 1][1] = r[3];
                ldsm4(r, sptr(Kl + n * 72 + col));
                kl[2 * p][0] = r[0]; kl[2 * p][1] = r[1];
                kl[2 * p + 1][0] = r[2]; kl[2 * p + 1][1] = r[3];
            }
#pragma unroll
            for (int j = 0; j < 8; j++) {
                mma16816(S[j], qh, kh[j]);
                mma16816(S[j], qh, kl[j]);
                mma16816(S[j], ql, kh[j]);
            }
        }

        float fac[2];
#pragma unroll
        for (int h2 = 0; h2 < 2; h2++) {
            float rm = -1e30f;
#pragma unroll
            for (int j = 0; j < 8; j++)
                rm = fmaxf(rm, fmaxf(S[j][2 * h2], S[j][2 * h2 + 1]));
            rm = fmaxf(rm, __shfl_xor_sync(0xffffffffu, rm, 1));
            rm = fmaxf(rm, __shfl_xor_sync(0xffffffffu, rm, 2));
            float mn = fmaxf(m_[h2], rm);
            fac[h2] = __expf(m_[h2] - mn);
            float rsum = 0.f;
#pragma unroll
            for (int j = 0; j < 8; j++) {
                float p0 = __expf(S[j][2 * h2] - mn);
                float p1 = __expf(S[j][2 * h2 + 1] - mn);
                S[j][2 * h2] = p0; S[j][2 * h2 + 1] = p1;
                rsum += p0 + p1;
            }
            rsum += __shfl_xor_sync(0xffffffffu, rsum, 1);
            rsum += __shfl_xor_sync(0xffffffffu, rsum, 2);
            l_[h2] = l_[h2] * fac[h2] + rsum;
            m_[h2] = mn;
        }
#pragma unroll
        for (int j = 0; j < 8; j++) {
            O[j][0] *= fac[0]; O[j][1] *= fac[0];
            O[j][2] *= fac[1]; O[j][3] *= fac[1];
        }

#pragma unroll
        for (int ks = 0; ks < 4; ks++) {
            uint32_t ph[4], pl[4];
            split_pack(S[2 * ks][0], S[2 * ks][1], ph[0], pl[0]);
            split_pack(S[2 * ks][2], S[2 * ks][3], ph[1], pl[1]);
            split_pack(S[2 * ks + 1][0], S[2 * ks + 1][1], ph[2], pl[2]);
            split_pack(S[2 * ks + 1][2], S[2 * ks + 1][3], ph[3], pl[3]);
            uint32_t vh[8][2], vl[8][2];
#pragma unroll
            for (int p = 0; p < 4; p++) {
                uint32_t r[4];
                int k = ks * 16 + ((lane >> 3) & 1) * 8 + (lane & 7);
                int n = p * 16 + ((lane >> 4) & 1) * 8;
                ldsm4t(r, sptr(Vh + k * 72 + n));
                vh[2 * p][0] = r[0]; vh[2 * p][1] = r[1];
                vh[2 * p + 1][0] = r[2]; vh[2 * p + 1][1] = r[3];
                ldsm4t(r, sptr(Vl + k * 72 + n));
                vl[2 * p][0] = r[0]; vl[2 * p][1] = r[1];
                vl[2 * p + 1][0] = r[2]; vl[2 * p + 1][1] = r[3];
            }
#pragma unroll
            for (int j = 0; j < 8; j++) {
                mma16816(O[j], ph, vh[j]);
                mma16816(O[j], ph, vl[j]);
                mma16816(O[j], pl, vh[j]);
            }
        }
    }

    float inv0 = 1.f / l_[0], inv1 = 1.f / l_[1];
    int r0 = tok0 + wq + (lane >> 2);
#pragma unroll
    for (int j = 0; j < 8; j++) {
        int col = h * HDIM + j * 8 + (lane & 3) * 2;
        split2_store(oh + (size_t)r0 * DMODEL + col, ol + (size_t)r0 * DMODEL + col,
                     O[j][0] * inv0, O[j][1] * inv0);
        split2_store(oh + (size_t)(r0 + 8) * DMODEL + col, ol + (size_t)(r0 + 8) * DMODEL + col,
                     O[j][2] * inv1, O[j][3] * inv1);
    }
}

// ---------------- gate / bucketing -------------------------------------------------
__global__ void zero_kernel() {
    if (threadIdx.x < NTILES) { g_cnt[threadIdx.x] = 0; g_fill[threadIdx.x] = 0; }
}

__global__ void gate_kernel(const float* __restrict__ n2, const float* __restrict__ gw,
                            const float* __restrict__ gb, float* __restrict__ gate_out) {
    int t = blockIdx.x;
    const float* xr = n2 + (size_t)t * DMODEL;
    float lg[NTILES] = {};
    for (int d = threadIdx.x; d < DMODEL; d += 256) {
        float v = xr[d];
#pragma unroll
        for (int e = 0; e < NTILES; e++) lg[e] += v * gw[e * DMODEL + d];
    }
#pragma unroll
    for (int o = 16; o; o >>= 1)
#pragma unroll
        for (int e = 0; e < NTILES; e++) lg[e] += __shfl_xor_sync(0xffffffffu, lg[e], o);
    __shared__ float smv[8][NTILES];
    if ((threadIdx.x & 31) == 0)
#pragma unroll
        for (int e = 0; e < NTILES; e++) smv[threadIdx.x >> 5][e] = lg[e];
    __syncthreads();
    if (threadIdx.x == 0) {
        int best = 0; float bv = -1e30f;
#pragma unroll
        for (int e = 0; e < NTILES; e++) {
            float v = gb[e];
#pragma unroll
            for (int w = 0; w < 8; w++) v += smv[w][e];
            if (v > bv) { bv = v; best = e; }
        }
        g_tile_id[t] = best;
#pragma unroll
        for (int e = 0; e < NTILES; e++) gate_out[(size_t)t * NTILES + e] = (e == best) ? 1.f : 0.f;
        atomicAdd(&g_cnt[best], 1);
    }
}

__global__ void scan_kernel() {
    if (threadIdx.x == 0) {
        int a = 0;
        for (int e = 0; e < NTILES; e++) { g_off[e] = a; a += g_cnt[e]; }
    }
}

__global__ void scatter_kernel() {
    int t = blockIdx.x * 256 + threadIdx.x;
    int e = g_tile_id[t];
    int p = atomicAdd(&g_fill[e], 1);
    g_perm[g_off[e] + p] = t;
}

// ---------------- launch ------------------------------------------------------------
extern "C" void kernel_launch(void* const* d_in, const int* in_sizes, int n_in,
                              void* d_out, int out_size) {
    const float* x      = (const float*)d_in[0];
    const float* ln1_g  = (const float*)d_in[1];
    const float* ln1_b  = (const float*)d_in[2];
    const float* qkv_w  = (const float*)d_in[3];
    const float* qkv_b  = (const float*)d_in[4];
    const float* out_w  = (const float*)d_in[5];
    const float* out_b  = (const float*)d_in[6];
    const float* ln2_g  = (const float*)d_in[7];
    const float* ln2_b  = (const float*)d_in[8];
    const float* gate_w = (const float*)d_in[9];
    const float* gate_b = (const float*)d_in[10];
    const float* up_W   = (const float*)d_in[11];
    const float* up_b   = (const float*)d_in[12];
    const float* down_W = (const float*)d_in[13];
    const float* down_b = (const float*)d_in[14];

    float* outp = (float*)d_out;
    float* gate_out = outp + (size_t)NTOK * DMODEL;

    void* p;
    cudaGetSymbolAddress(&p, g_qkv);    float* qkv  = (float*)p;
    cudaGetSymbolAddress(&p, g_xres);   float* xres = (float*)p;
    cudaGetSymbolAddress(&p, g_n2);     float* n2   = (float*)p;
    cudaGetSymbolAddress(&p, g_n1h);    __nv_bfloat16* n1h = (__nv_bfloat16*)p;
    cudaGetSymbolAddress(&p, g_n1l);    __nv_bfloat16* n1l = (__nv_bfloat16*)p;
    cudaGetSymbolAddress(&p, g_attnh);  __nv_bfloat16* ath = (__nv_bfloat16*)p;
    cudaGetSymbolAddress(&p, g_attnl);  __nv_bfloat16* atl = (__nv_bfloat16*)p;
    cudaGetSymbolAddress(&p, g_n2h);    __nv_bfloat16* n2h = (__nv_bfloat16*)p;
    cudaGetSymbolAddress(&p, g_n2l);    __nv_bfloat16* n2l = (__nv_bfloat16*)p;
    cudaGetSymbolAddress(&p, g_h_hi);   __nv_bfloat16* hh = (__nv_bfloat16*)p;
    cudaGetSymbolAddress(&p, g_h_lo);   __nv_bfloat16* hl = (__nv_bfloat16*)p;
    cudaGetSymbolAddress(&p, g_qkvw_h); __nv_bfloat16* qwh = (__nv_bfloat16*)p;
    cudaGetSymbolAddress(&p, g_qkvw_l); __nv_bfloat16* qwl = (__nv_bfloat16*)p;
    cudaGetSymbolAddress(&p, g_outw_h); __nv_bfloat16* owh = (__nv_bfloat16*)p;
    cudaGetSymbolAddress(&p, g_outw_l); __nv_bfloat16* owl = (__nv_bfloat16*)p;
    cudaGetSymbolAddress(&p, g_upw_h);  __nv_bfloat16* uwh = (__nv_bfloat16*)p;
    cudaGetSymbolAddress(&p, g_upw_l);  __nv_bfloat16* uwl = (__nv_bfloat16*)p;
    cudaGetSymbolAddress(&p, g_dnw_h);  __nv_bfloat16* dwh = (__nv_bfloat16*)p;
    cudaGetSymbolAddress(&p, g_dnw_l);  __nv_bfloat16* dwl = (__nv_bfloat16*)p;

    const int smem_attn = 27648 * 2;
    cudaFuncSetAttribute(gemm_cp<0>, cudaFuncAttributeMaxDynamicSharedMemorySize, GSMEM);
    cudaFuncSetAttribute(gemm_cp<1>, cudaFuncAttributeMaxDynamicSharedMemorySize, GSMEM);
    cudaFuncSetAttribute(gemm_cp<2>, cudaFuncAttributeMaxDynamicSharedMemorySize, GSMEM);
    cudaFuncSetAttribute(gemm_cp<3>, cudaFuncAttributeMaxDynamicSharedMemorySize, GSMEM);
    cudaFuncSetAttribute(attn_mma, cudaFuncAttributeMaxDynamicSharedMemorySize, smem_attn);

    // 0) weight pre-split (+transpose for FFN weights)
    wsplit<<<D3 * DMODEL / 1024, 256>>>(qkv_w, qwh, qwl);
    wsplit<<<DMODEL * DMODEL / 1024, 256>>>(out_w, owh, owl);
    wsplit_t<<<dim3(DFF / 32, DMODEL / 32, NTILES), dim3(32, 8)>>>(up_W, uwh, uwl, DMODEL, DFF);
    wsplit_t<<<dim3(DMODEL / 32, DFF / 32, NTILES), dim3(32, 8)>>>(down_W, dwh, dwl, DFF, DMODEL);

    // 1) LN1 (split output only)
    ln_split<false><<<NTOK, 256>>>(x, ln1_g, ln1_b, nullptr, n1h, n1l);
    // 2) QKV projection
    gemm_cp<0><<<dim3(D3 / 128, NTOK / 128), 256, GSMEM>>>(
        n1h, n1l, qwh, qwl, qkv_b, nullptr, qkv, nullptr, nullptr, D3, DMODEL);
    // 3) attention -> split output
    attn_mma<<<dim3(SEQ / 64, NHEAD, NB), 128, smem_attn>>>(qkv, ath, atl);
    // 4) out projection + residual
    gemm_cp<1><<<dim3(DMODEL / 128, NTOK / 128), 256, GSMEM>>>(
        ath, atl, owh, owl, out_b, x, xres, nullptr, nullptr, DMODEL, DMODEL);
    // 5) LN2 (fp32 + split)
    ln_split<true><<<NTOK, 256>>>(xres, ln2_g, ln2_b, n2, n2h, n2l);
    // 6) gate + bucketing
    zero_kernel<<<1, 32>>>();
    gate_kernel<<<NTOK, 256>>>(n2, gate_w, gate_b, gate_out);
    scan_kernel<<<1, 32>>>();
    scatter_kernel<<<NTOK / 256, 256>>>();
    // 7) FFN
    gemm_cp<2><<<dim3(DFF / 128, NTOK / 128, NTILES), 256, GSMEM>>>(
        n2h, n2l, uwh, uwl, up_b, nullptr, nullptr, hh, hl, DFF, DMODEL);
    gemm_cp<3><<<dim3(DMODEL / 128, NTOK / 128, NTILES), 256, GSMEM>>>(
        hh, hl, dwh, dwl, down_b, xres, outp, nullptr, nullptr, DMODEL, DFF);
}

// round 7
// speedup vs baseline: 1.0518x; 1.0518x over previous
#include <cuda_runtime.h>
#include <cuda_bf16.h>
#include <math.h>
#include <stdint.h>

#define NTOK 4096
#define DMODEL 1024
#define D3 3072
#define NHEAD 16
#define HDIM 64
#define SEQ 1024
#define NB 4
#define NTILES 8
#define DFF 4096

// ---------------- scratch (device globals) -------------------------------------
__device__ float g_qkv[NTOK * D3];
__device__ float g_xres[NTOK * DMODEL];
__device__ float g_n2[NTOK * DMODEL];
__device__ __nv_bfloat16 g_n1h[NTOK * DMODEL], g_n1l[NTOK * DMODEL];
__device__ __nv_bfloat16 g_attnh[NTOK * DMODEL], g_attnl[NTOK * DMODEL];
__device__ __nv_bfloat16 g_n2h[NTOK * DMODEL], g_n2l[NTOK * DMODEL];
__device__ __nv_bfloat16 g_h_hi[(size_t)NTOK * DFF], g_h_lo[(size_t)NTOK * DFF];
// pre-split weights (same layout as source: qkv/out [N,K]; up/down [K,N])
__device__ __nv_bfloat16 g_qkvw_h[D3 * DMODEL], g_qkvw_l[D3 * DMODEL];
__device__ __nv_bfloat16 g_outw_h[DMODEL * DMODEL], g_outw_l[DMODEL * DMODEL];
__device__ __nv_bfloat16 g_upw_h[(size_t)NTILES * DMODEL * DFF];
__device__ __nv_bfloat16 g_upw_l[(size_t)NTILES * DMODEL * DFF];
__device__ __nv_bfloat16 g_dnw_h[(size_t)NTILES * DFF * DMODEL];
__device__ __nv_bfloat16 g_dnw_l[(size_t)NTILES * DFF * DMODEL];
__device__ int g_tile_id[NTOK];
__device__ int g_perm[NTOK];
__device__ int g_cnt[NTILES];
__device__ int g_off[NTILES];
__device__ int g_fill[NTILES];

// ---------------- helpers -------------------------------------------------------
__device__ __forceinline__ uint32_t sptr(const void* p) {
    return (uint32_t)__cvta_generic_to_shared(p);
}
__device__ __forceinline__ uint32_t pack_bf2(__nv_bfloat16 a, __nv_bfloat16 b) {
    return (uint32_t)__bfloat16_as_ushort(a) | ((uint32_t)__bfloat16_as_ushort(b) << 16);
}
__device__ __forceinline__ void split4(float4 v, __nv_bfloat16* hi, __nv_bfloat16* lo) {
    float a[4] = {v.x, v.y, v.z, v.w};
    __nv_bfloat16 h[4], l[4];
#pragma unroll
    for (int i = 0; i < 4; i++) {
        h[i] = __float2bfloat16(a[i]);
        l[i] = __float2bfloat16(a[i] - __bfloat162float(h[i]));
    }
    *(uint32_t*)(hi)     = pack_bf2(h[0], h[1]);
    *(uint32_t*)(hi + 2) = pack_bf2(h[2], h[3]);
    *(uint32_t*)(lo)     = pack_bf2(l[0], l[1]);
    *(uint32_t*)(lo + 2) = pack_bf2(l[2], l[3]);
}
__device__ __forceinline__ void split2_store(__nv_bfloat16* hi, __nv_bfloat16* lo,
                                             float v0, float v1) {
    __nv_bfloat16 h0 = __float2bfloat16(v0), h1 = __float2bfloat16(v1);
    __nv_bfloat16 l0 = __float2bfloat16(v0 - __bfloat162float(h0));
    __nv_bfloat16 l1 = __float2bfloat16(v1 - __bfloat162float(h1));
    *(uint32_t*)hi = pack_bf2(h0, h1);
    *(uint32_t*)lo = pack_bf2(l0, l1);
}
__device__ __forceinline__ void split_pack(float x, float y, uint32_t& hi, uint32_t& lo) {
    __nv_bfloat16 hx = __float2bfloat16(x), hy = __float2bfloat16(y);
    __nv_bfloat16 lx = __float2bfloat16(x - __bfloat162float(hx));
    __nv_bfloat16 ly = __float2bfloat16(y - __bfloat162float(hy));
    hi = pack_bf2(hx, hy);
    lo = pack_bf2(lx, ly);
}
__device__ __forceinline__ void ldsm4(uint32_t* r, uint32_t a) {
    asm volatile("ldmatrix.sync.aligned.m8n8.x4.shared.b16 {%0,%1,%2,%3}, [%4];"
                 : "=r"(r[0]), "=r"(r[1]), "=r"(r[2]), "=r"(r[3]) : "r"(a));
}
__device__ __forceinline__ void ldsm4t(uint32_t* r, uint32_t a) {
    asm volatile("ldmatrix.sync.aligned.m8n8.x4.trans.shared.b16 {%0,%1,%2,%3}, [%4];"
                 : "=r"(r[0]), "=r"(r[1]), "=r"(r[2]), "=r"(r[3]) : "r"(a));
}
__device__ __forceinline__ void mma16816(float* c, const uint32_t* a, const uint32_t* b) {
    asm volatile(
        "mma.sync.aligned.m16n8k16.row.col.f32.bf16.bf16.f32 "
        "{%0,%1,%2,%3}, {%4,%5,%6,%7}, {%8,%9}, {%0,%1,%2,%3};"
        : "+f"(c[0]), "+f"(c[1]), "+f"(c[2]), "+f"(c[3])
        : "r"(a[0]), "r"(a[1]), "r"(a[2]), "r"(a[3]), "r"(b[0]), "r"(b[1]));
}
__device__ __forceinline__ void cpa16(uint32_t s, const void* g) {
    asm volatile("cp.async.cg.shared.global [%0], [%1], 16;" :: "r"(s), "l"(g));
}
#define CP_COMMIT() asm volatile("cp.async.commit_group;" ::: "memory")
#define CP_WAIT2() asm volatile("cp.async.wait_group 2;" ::: "memory")
#define CP_WAIT0() asm volatile("cp.async.wait_group 0;" ::: "memory")

// one 32-wide K chunk: 3-pass compensated bf16. Warp tile 32x32 (acc[2][4][4]).
// A K-major stride 40. B: BT=false K-major stride 40 (ldsm), BT=true MN-major
// stride 136 (ldsm trans).
template <bool BT, int BSTR>
__device__ __forceinline__ void mma_compute(const __nv_bfloat16* As_hi, const __nv_bfloat16* As_lo,
                                            const __nv_bfloat16* Bs_hi, const __nv_bfloat16* Bs_lo,
                                            float (*acc)[4][4], int lane, int wm, int wn) {
#pragma unroll
    for (int s = 0; s < 2; s++) {
        const int ks = s * 16;
        uint32_t ah[2][4], al[2][4], bh[4][2], bl[4][2];
#pragma unroll
        for (int mi = 0; mi < 2; mi++) {
            int row = wm * 32 + mi * 16 + (lane & 15);
            int col = ks + ((lane >> 4) & 1) * 8;
            ldsm4(ah[mi], sptr(As_hi + row * 40 + col));
            ldsm4(al[mi], sptr(As_lo + row * 40 + col));
        }
#pragma unroll
        for (int p = 0; p < 2; p++) {
            uint32_t r[4];
            uint32_t adr_h, adr_l;
            if (!BT) {
                int n = wn * 32 + p * 16 + ((lane >> 4) & 1) * 8 + (lane & 7);
                int col = ks + ((lane >> 3) & 1) * 8;
                adr_h = sptr(Bs_hi + n * BSTR + col);
                adr_l = sptr(Bs_lo + n * BSTR + col);
                ldsm4(r, adr_h);
            } else {
                int k = ks + ((lane >> 3) & 1) * 8 + (lane & 7);
                int n = wn * 32 + p * 16 + ((lane >> 4) & 1) * 8;
                adr_h = sptr(Bs_hi + k * BSTR + n);
                adr_l = sptr(Bs_lo + k * BSTR + n);
                ldsm4t(r, adr_h);
            }
            bh[2 * p][0] = r[0]; bh[2 * p][1] = r[1];
            bh[2 * p + 1][0] = r[2]; bh[2 * p + 1][1] = r[3];
            if (!BT) ldsm4(r, adr_l); else ldsm4t(r, adr_l);
            bl[2 * p][0] = r[0]; bl[2 * p][1] = r[1];
            bl[2 * p + 1][0] = r[2]; bl[2 * p + 1][1] = r[3];
        }
#pragma unroll
        for (int mi = 0; mi < 2; mi++)
#pragma unroll
            for (int ni = 0; ni < 4; ni++) {
                mma16816(acc[mi][ni], ah[mi], bh[ni]);
                mma16816(acc[mi][ni], ah[mi], bl[ni]);
                mma16816(acc[mi][ni], al[mi], bh[ni]);
            }
    }
}

// ---------------- weight pre-split (elementwise only) ------------------------------
__global__ void wsplit(const float* __restrict__ src, __nv_bfloat16* __restrict__ dh,
                       __nv_bfloat16* __restrict__ dl) {
    size_t i = (size_t)blockIdx.x * 256 + threadIdx.x;
    float4 v = *(const float4*)(src + i * 4);
    split4(v, dh + i * 4, dl + i * 4);
}

// ---------------- GEMM: C[M,N] = A[M,K] * B^T, pre-split bf16, cp.async, 512 thr ---
// MODE 0: +bias -> fp32 C          MODE 1: +bias +resid -> fp32 C
// MODE 2: gather A rows via perm, +bias, relu -> split Oh/Ol (compact), BT
// MODE 3: A compact (off+row), +bias +resid, scatter -> fp32 C, BT
#define GSTG_NT 40960  // A hi/lo 2*10240 + B(K-major) hi/lo 2*10240
#define GSTG_T  37888  // A hi/lo 2*10240 + B(MN-major 32x136) hi/lo 2*8704

template <int MODE, bool BT>
__global__ __launch_bounds__(512, 1) void gemm_cp(
    const __nv_bfloat16* __restrict__ Ah, const __nv_bfloat16* __restrict__ Al,
    const __nv_bfloat16* __restrict__ Wh, const __nv_bfloat16* __restrict__ Wl,
    const float* __restrict__ bias, const float* __restrict__ resid,
    float* __restrict__ C, __nv_bfloat16* __restrict__ Oh, __nv_bfloat16* __restrict__ Ol,
    int N, int K) {
    constexpr int STG = BT ? GSTG_T : GSTG_NT;
    constexpr int BOFF = 20480;               // byte offset of Bh in stage
    constexpr int BSZ = BT ? 8704 : 10240;    // bytes per B array
    extern __shared__ __nv_bfloat16 dsm[];
    const int tid = threadIdx.x, lane = tid & 31, w = tid >> 5;
    const int wm = w & 3, wn = w >> 2;
    const int bn = blockIdx.x * 128, bm = blockIdx.y * 128;
    int cnt = 0, off = 0;
    if (MODE >= 2) {
        const int t = blockIdx.z;
        cnt = g_cnt[t];
        if (bm >= cnt) return;
        off = g_off[t];
        Wh += (size_t)t * N * K;
        Wl += (size_t)t * N * K;
        bias += (size_t)t * N;
    }
    const uint32_t sb = sptr(dsm);
    // fill-role precompute (one pass per thread: 4x cpa16)
    const int ar = tid >> 2, ach = tid & 3;               // A: row 0..127, 16B chunk 0..3
    const uint32_t adst = (uint32_t)(ar * 80 + ach * 16);
    size_t abase;
    if (MODE <= 1) {
        abase = (size_t)(bm + ar) * K;
    } else if (MODE == 2) {
        int gr = bm + ar;
        int tok = (gr < cnt) ? g_perm[off + gr] : 0;
        abase = (size_t)tok * K;
    } else {
        int gr = bm + ar;
        abase = (size_t)(off + ((gr < cnt) ? gr : 0)) * K;
    }
    size_t bbase;
    uint32_t bdst;
    int bch;
    if (!BT) {
        bbase = (size_t)(bn + ar) * K;        // row = n, chunk = ach (k dir)
        bdst = (uint32_t)(BOFF + ar * 80 + ach * 16);
        bch = ach;
    } else {
        int bk = tid >> 4;                    // 0..31 (k row)
        bch = tid & 15;                       // 0..15 (16B chunk along n)
        bbase = (size_t)bk * N + bn;          // + k0*N at fill time
        bdst = (uint32_t)(BOFF + bk * 272 + bch * 16);
    }
    const int NC = K >> 5;
    auto fill = [&](int s, int c) {
        const int k0 = c * 32;
        const uint32_t st = sb + s * STG;
        cpa16(st + adst,         Ah + abase + k0 + ach * 8);
        cpa16(st + 10240 + adst, Al + abase + k0 + ach * 8);
        if (!BT) {
            cpa16(st + bdst,       Wh + bbase + k0 + bch * 8);
            cpa16(st + BSZ + bdst, Wl + bbase + k0 + bch * 8);
        } else {
            cpa16(st + bdst,       Wh + bbase + (size_t)k0 * N + bch * 8);
            cpa16(st + BSZ + bdst, Wl + bbase + (size_t)k0 * N + bch * 8);
        }
        CP_COMMIT();
    };
    fill(0, 0);
    fill(1, 1);
    fill(2, 2);
    float acc[2][4][4] = {};
    for (int c = 0; c < NC; c++) {
        if (c + 3 < NC) CP_WAIT2(); else CP_WAIT0();
        __syncthreads();
        if (c + 3 < NC) fill((c + 3) & 3, c + 3);
        const __nv_bfloat16* b0 = dsm + (c & 3) * (STG / 2);
        mma_compute<BT, BT ? 136 : 40>(b0, b0 + 5120, b0 + BOFF / 2, b0 + (BOFF + BSZ) / 2,
                                       acc, lane, wm, wn);
    }
    // ---- epilogue
#pragma unroll
    for (int mi = 0; mi < 2; mi++) {
        int r0 = bm + wm * 32 + mi * 16 + (lane >> 2);
#pragma unroll
        for (int ni = 0; ni < 4; ni++) {
            int cn = bn + wn * 32 + ni * 8 + (lane & 3) * 2;
            float2 bs = *(const float2*)(bias + cn);
            if (MODE <= 1) {
                float2 o0 = make_float2(acc[mi][ni][0] + bs.x, acc[mi][ni][1] + bs.y);
                float2 o1 = make_float2(acc[mi][ni][2] + bs.x, acc[mi][ni][3] + bs.y);
                if (MODE == 1) {
                    float2 ra = *(const float2*)(resid + (size_t)r0 * N + cn);
                    float2 rb = *(const float2*)(resid + (size_t)(r0 + 8) * N + cn);
                    o0.x += ra.x; o0.y += ra.y; o1.x += rb.x; o1.y += rb.y;
                }
                *(float2*)(C + (size_t)r0 * N + cn) = o0;
                *(float2*)(C + (size_t)(r0 + 8) * N + cn) = o1;
            } else if (MODE == 2) {
                int la = r0;
                if (la < cnt) {
                    float v0 = fmaxf(acc[mi][ni][0] + bs.x, 0.f);
                    float v1 = fmaxf(acc[mi][ni][1] + bs.y, 0.f);
                    split2_store(Oh + (size_t)(off + la) * N + cn,
                                 Ol + (size_t)(off + la) * N + cn, v0, v1);
                }
                if (la + 8 < cnt) {
                    float v2 = fmaxf(acc[mi][ni][2] + bs.x, 0.f);
                    float v3 = fmaxf(acc[mi][ni][3] + bs.y, 0.f);
                    split2_store(Oh + (size_t)(off + la + 8) * N + cn,
                                 Ol + (size_t)(off + la + 8) * N + cn, v2, v3);
                }
            } else {  // MODE 3
                int la = r0;
                if (la < cnt) {
                    int tok = g_perm[off + la];
                    float2 xr = *(const float2*)(resid + (size_t)tok * N + cn);
                    *(float2*)(C + (size_t)tok * N + cn) =
                        make_float2(acc[mi][ni][0] + bs.x + xr.x, acc[mi][ni][1] + bs.y + xr.y);
                }
                if (la + 8 < cnt) {
                    int tok = g_perm[off + la + 8];
                    float2 xr = *(const float2*)(resid + (size_t)tok * N + cn);
                    *(float2*)(C + (size_t)tok * N + cn) =
                        make_float2(acc[mi][ni][2] + bs.x + xr.x, acc[mi][ni][3] + bs.y + xr.y);
                }
            }
        }
    }
}

// ---------------- layernorm with split output -------------------------------------
template <bool FP32OUT>
__global__ void ln_split(const float* __restrict__ x, const float* __restrict__ g,
                         const float* __restrict__ bb, float* __restrict__ y,
                         __nv_bfloat16* __restrict__ yh, __nv_bfloat16* __restrict__ yl) {
    int t = blockIdx.x;
    const float* xr = x + (size_t)t * DMODEL;
    int d = threadIdx.x * 4;
    float4 v = *(const float4*)(xr + d);
    float s = v.x + v.y + v.z + v.w;
    float s2 = v.x * v.x + v.y * v.y + v.z * v.z + v.w * v.w;
#pragma unroll
    for (int o = 16; o; o >>= 1) {
        s += __shfl_xor_sync(0xffffffffu, s, o);
        s2 += __shfl_xor_sync(0xffffffffu, s2, o);
    }
    __shared__ float rs[8], rq[8];
    if ((threadIdx.x & 31) == 0) { rs[threadIdx.x >> 5] = s; rq[threadIdx.x >> 5] = s2; }
    __syncthreads();
    __shared__ float smean, srstd;
    if (threadIdx.x == 0) {
        float a = 0.f, b2 = 0.f;
#pragma unroll
        for (int i = 0; i < 8; i++) { a += rs[i]; b2 += rq[i]; }
        float mean = a * (1.f / DMODEL);
        float var = b2 * (1.f / DMODEL) - mean * mean;
        smean = mean; srstd = rsqrtf(var + 1e-5f);
    }
    __syncthreads();
    float mean = smean, rstd = srstd;
    float4 gv = *(const float4*)(g + d);
    float4 bv = *(const float4*)(bb + d);
    float4 o;
    o.x = (v.x - mean) * rstd * gv.x + bv.x;
    o.y = (v.y - mean) * rstd * gv.y + bv.y;
    o.z = (v.z - mean) * rstd * gv.z + bv.z;
    o.w = (v.w - mean) * rstd * gv.w + bv.w;
    if (FP32OUT) *(float4*)(y + (size_t)t * DMODEL + d) = o;
    split4(o, yh + (size_t)t * DMODEL + d, yl + (size_t)t * DMODEL + d);
}

// ---------------- MMA flash attention (split output) ------------------------------
__global__ __launch_bounds__(128) void attn_mma(const float* __restrict__ qkv,
                                                __nv_bfloat16* __restrict__ oh,
                                                __nv_bfloat16* __restrict__ ol) {
    extern __shared__ __nv_bfloat16 asm_[];
    __nv_bfloat16* Qh = asm_;
    __nv_bfloat16* Ql = asm_ + 4608;
    __nv_bfloat16* Kh = asm_ + 9216;
    __nv_bfloat16* Kl = asm_ + 13824;
    __nv_bfloat16* Vh = asm_ + 18432;
    __nv_bfloat16* Vl = asm_ + 23040;

    const int qt = blockIdx.x, h = blockIdx.y, b = blockIdx.z;
    const int tid = threadIdx.x, lane = tid & 31, wid = tid >> 5;
    const int tok0 = b * SEQ + qt * 64;
    const int wq = wid * 16;

#pragma unroll
    for (int i = 0; i < 8; i++) {
        int idx = i * 128 + tid;
        int row = idx >> 4, col = (idx & 15) * 4;
        float4 v = *(const float4*)(qkv + (size_t)(tok0 + row) * D3 + h * HDIM + col);
        v.x *= 0.125f; v.y *= 0.125f; v.z *= 0.125f; v.w *= 0.125f;
        split4(v, Qh + row * 72 + col, Ql + row * 72 + col);
    }

    float m_[2] = {-1e30f, -1e30f}, l_[2] = {0.f, 0.f};
    float O[8][4] = {};

    for (int kt = 0; kt < 16; kt++) {
        int kb = b * SEQ + kt * 64;
        __syncthreads();
#pragma unroll
        for (int i = 0; i < 8; i++) {
            int idx = i * 128 + tid;
            int row = idx >> 4, col = (idx & 15) * 4;
            const float* base = qkv + (size_t)(kb + row) * D3 + h * HDIM + col;
            float4 kv = *(const float4*)(base + DMODEL);
            split4(kv, Kh + row * 72 + col, Kl + row * 72 + col);
            float4 vv = *(const float4*)(base + 2 * DMODEL);
            split4(vv, Vh + row * 72 + col, Vl + row * 72 + col);
        }
        __syncthreads();

        float S[8][4] = {};
#pragma unroll
        for (int ks = 0; ks < 4; ks++) {
            uint32_t qh[4], ql[4], kh[8][2], kl[8][2];
            {
                int row = wq + (lane & 15);
                int col = ks * 16 + ((lane >> 4) & 1) * 8;
                ldsm4(qh, sptr(Qh + row * 72 + col));
                ldsm4(ql, sptr(Ql + row * 72 + col));
            }
#pragma unroll
            for (int p = 0; p < 4; p++) {
                uint32_t r[4];
                int n = p * 16 + ((lane >> 4) & 1) * 8 + (lane & 7);
                int col = ks * 16 + ((lane >> 3) & 1) * 8;
                ldsm4(r, sptr(Kh + n * 72 + col));
                kh[2 * p][0] = r[0]; kh[2 * p][1] = r[1];
                kh[2 * p + 1][0] = r[2]; kh[2 * p + 1][1] = r[3];
                ldsm4(r, sptr(Kl + n * 72 + col));
                kl[2 * p][0] = r[0]; kl[2 * p][1] = r[1];
                kl[2 * p + 1][0] = r[2]; kl[2 * p + 1][1] = r[3];
            }
#pragma unroll
            for (int j = 0; j < 8; j++) {
                mma16816(S[j], qh, kh[j]);
                mma16816(S[j], qh, kl[j]);
                mma16816(S[j], ql, kh[j]);
            }
        }

        float fac[2];
#pragma unroll
        for (int h2 = 0; h2 < 2; h2++) {
            float rm = -1e30f;
#pragma unroll
            for (int j = 0; j < 8; j++)
                rm = fmaxf(rm, fmaxf(S[j][2 * h2], S[j][2 * h2 + 1]));
            rm = fmaxf(rm, __shfl_xor_sync(0xffffffffu, rm, 1));
            rm = fmaxf(rm, __shfl_xor_sync(0xffffffffu, rm, 2));
            float mn = fmaxf(m_[h2], rm);
            fac[h2] = __expf(m_[h2] - mn);
            float rsum = 0.f;
#pragma unroll
            for (int j = 0; j < 8; j++) {
                float p0 = __expf(S[j][2 * h2] - mn);
                float p1 = __expf(S[j][2 * h2 + 1] - mn);
                S[j][2 * h2] = p0; S[j][2 * h2 + 1] = p1;
                rsum += p0 + p1;
            }
            rsum += __shfl_xor_sync(0xffffffffu, rsum, 1);
            rsum += __shfl_xor_sync(0xffffffffu, rsum, 2);
            l_[h2] = l_[h2] * fac[h2] + rsum;
            m_[h2] = mn;
        }
#pragma unroll
        for (int j = 0; j < 8; j++) {
            O[j][0] *= fac[0]; O[j][1] *= fac[0];
            O[j][2] *= fac[1]; O[j][3] *= fac[1];
        }

#pragma unroll
        for (int ks = 0; ks < 4; ks++) {
            uint32_t ph[4], pl[4];
            split_pack(S[2 * ks][0], S[2 * ks][1], ph[0], pl[0]);
            split_pack(S[2 * ks][2], S[2 * ks][3], ph[1], pl[1]);
            split_pack(S[2 * ks + 1][0], S[2 * ks + 1][1], ph[2], pl[2]);
            split_pack(S[2 * ks + 1][2], S[2 * ks + 1][3], ph[3], pl[3]);
            uint32_t vh[8][2], vl[8][2];
#pragma unroll
            for (int p = 0; p < 4; p++) {
                uint32_t r[4];
                int k = ks * 16 + ((lane >> 3) & 1) * 8 + (lane & 7);
                int n = p * 16 + ((lane >> 4) & 1) * 8;
                ldsm4t(r, sptr(Vh + k * 72 + n));
                vh[2 * p][0] = r[0]; vh[2 * p][1] = r[1];
                vh[2 * p + 1][0] = r[2]; vh[2 * p + 1][1] = r[3];
                ldsm4t(r, sptr(Vl + k * 72 + n));
                vl[2 * p][0] = r[0]; vl[2 * p][1] = r[1];
                vl[2 * p + 1][0] = r[2]; vl[2 * p + 1][1] = r[3];
            }
#pragma unroll
            for (int j = 0; j < 8; j++) {
                mma16816(O[j], ph, vh[j]);
                mma16816(O[j], ph, vl[j]);
                mma16816(O[j], pl, vh[j]);
            }
        }
    }

    float inv0 = 1.f / l_[0], inv1 = 1.f / l_[1];
    int r0 = tok0 + wq + (lane >> 2);
#pragma unroll
    for (int j = 0; j < 8; j++) {
        int col = h * HDIM + j * 8 + (lane & 3) * 2;
        split2_store(oh + (size_t)r0 * DMODEL + col, ol + (size_t)r0 * DMODEL + col,
                     O[j][0] * inv0, O[j][1] * inv0);
        split2_store(oh + (size_t)(r0 + 8) * DMODEL + col, ol + (size_t)(r0 + 8) * DMODEL + col,
                     O[j][2] * inv1, O[j][3] * inv1);
    }
}

// ---------------- gate / bucketing -------------------------------------------------
__global__ void zero_kernel() {
    if (threadIdx.x < NTILES) { g_cnt[threadIdx.x] = 0; g_fill[threadIdx.x] = 0; }
}

__global__ void gate_kernel(const float* __restrict__ n2, const float* __restrict__ gw,
                            const float* __restrict__ gb, float* __restrict__ gate_out) {
    int t = blockIdx.x;
    const float* xr = n2 + (size_t)t * DMODEL;
    float lg[NTILES] = {};
    for (int d = threadIdx.x; d < DMODEL; d += 256) {
        float v = xr[d];
#pragma unroll
        for (int e = 0; e < NTILES; e++) lg[e] += v * gw[e * DMODEL + d];
    }
#pragma unroll
    for (int o = 16; o; o >>= 1)
#pragma unroll
        for (int e = 0; e < NTILES; e++) lg[e] += __shfl_xor_sync(0xffffffffu, lg[e], o);
    __shared__ float smv[8][NTILES];
    if ((threadIdx.x & 31) == 0)
#pragma unroll
        for (int e = 0; e < NTILES; e++) smv[threadIdx.x >> 5][e] = lg[e];
    __syncthreads();
    if (threadIdx.x == 0) {
        int best = 0; float bv = -1e30f;
#pragma unroll
        for (int e = 0; e < NTILES; e++) {
            float v = gb[e];
#pragma unroll
            for (int w = 0; w < 8; w++) v += smv[w][e];
            if (v > bv) { bv = v; best = e; }
        }
        g_tile_id[t] = best;
#pragma unroll
        for (int e = 0; e < NTILES; e++) gate_out[(size_t)t * NTILES + e] = (e == best) ? 1.f : 0.f;
        atomicAdd(&g_cnt[best], 1);
    }
}

__global__ void scan_kernel() {
    if (threadIdx.x == 0) {
        int a = 0;
        for (int e = 0; e < NTILES; e++) { g_off[e] = a; a += g_cnt[e]; }
    }
}

__global__ void scatter_kernel() {
    int t = blockIdx.x * 256 + threadIdx.x;
    int e = g_tile_id[t];
    int p = atomicAdd(&g_fill[e], 1);
    g_perm[g_off[e] + p] = t;
}

// ---------------- launch ------------------------------------------------------------
extern "C" void kernel_launch(void* const* d_in, const int* in_sizes, int n_in,
                              void* d_out, int out_size) {
    const float* x      = (const float*)d_in[0];
    const float* ln1_g  = (const float*)d_in[1];
    const float* ln1_b  = (const float*)d_in[2];
    const float* qkv_w  = (const float*)d_in[3];
    const float* qkv_b  = (const float*)d_in[4];
    const float* out_w  = (const float*)d_in[5];
    const float* out_b  = (const float*)d_in[6];
    const float* ln2_g  = (const float*)d_in[7];
    const float* ln2_b  = (const float*)d_in[8];
    const float* gate_w = (const float*)d_in[9];
    const float* gate_b = (const float*)d_in[10];
    const float* up_W   = (const float*)d_in[11];
    const float* up_b   = (const float*)d_in[12];
    const float* down_W = (const float*)d_in[13];
    const float* down_b = (const float*)d_in[14];

    float* outp = (float*)d_out;
    float* gate_out = outp + (size_t)NTOK * DMODEL;

    void* p;
    cudaGetSymbolAddress(&p, g_qkv);    float* qkv  = (float*)p;
    cudaGetSymbolAddress(&p, g_xres);   float* xres = (float*)p;
    cudaGetSymbolAddress(&p, g_n2);     float* n2   = (float*)p;
    cudaGetSymbolAddress(&p, g_n1h);    __nv_bfloat16* n1h = (__nv_bfloat16*)p;
    cudaGetSymbolAddress(&p, g_n1l);    __nv_bfloat16* n1l = (__nv_bfloat16*)p;
    cudaGetSymbolAddress(&p, g_attnh);  __nv_bfloat16* ath = (__nv_bfloat16*)p;
    cudaGetSymbolAddress(&p, g_attnl);  __nv_bfloat16* atl = (__nv_bfloat16*)p;
    cudaGetSymbolAddress(&p, g_n2h);    __nv_bfloat16* n2h = (__nv_bfloat16*)p;
    cudaGetSymbolAddress(&p, g_n2l);    __nv_bfloat16* n2l = (__nv_bfloat16*)p;
    cudaGetSymbolAddress(&p, g_h_hi);   __nv_bfloat16* hh = (__nv_bfloat16*)p;
    cudaGetSymbolAddress(&p, g_h_lo);   __nv_bfloat16* hl = (__nv_bfloat16*)p;
    cudaGetSymbolAddress(&p, g_qkvw_h); __nv_bfloat16* qwh = (__nv_bfloat16*)p;
    cudaGetSymbolAddress(&p, g_qkvw_l); __nv_bfloat16* qwl = (__nv_bfloat16*)p;
    cudaGetSymbolAddress(&p, g_outw_h); __nv_bfloat16* owh = (__nv_bfloat16*)p;
    cudaGetSymbolAddress(&p, g_outw_l); __nv_bfloat16* owl = (__nv_bfloat16*)p;
    cudaGetSymbolAddress(&p, g_upw_h);  __nv_bfloat16* uwh = (__nv_bfloat16*)p;
    cudaGetSymbolAddress(&p, g_upw_l);  __nv_bfloat16* uwl = (__nv_bfloat16*)p;
    cudaGetSymbolAddress(&p, g_dnw_h);  __nv_bfloat16* dwh = (__nv_bfloat16*)p;
    cudaGetSymbolAddress(&p, g_dnw_l);  __nv_bfloat16* dwl = (__nv_bfloat16*)p;

    const int smem_attn = 27648 * 2;
    const int smem_nt = 4 * GSTG_NT;
    const int smem_t = 4 * GSTG_T;
    cudaFuncSetAttribute(gemm_cp<0, false>, cudaFuncAttributeMaxDynamicSharedMemorySize, smem_nt);
    cudaFuncSetAttribute(gemm_cp<1, false>, cudaFuncAttributeMaxDynamicSharedMemorySize, smem_nt);
    cudaFuncSetAttribute(gemm_cp<2, true>, cudaFuncAttributeMaxDynamicSharedMemorySize, smem_t);
    cudaFuncSetAttribute(gemm_cp<3, true>, cudaFuncAttributeMaxDynamicSharedMemorySize, smem_t);
    cudaFuncSetAttribute(attn_mma, cudaFuncAttributeMaxDynamicSharedMemorySize, smem_attn);

    // 0) weight pre-split (elementwise; layouts preserved)
    wsplit<<<D3 * DMODEL / 1024, 256>>>(qkv_w, qwh, qwl);
    wsplit<<<DMODEL * DMODEL / 1024, 256>>>(out_w, owh, owl);
    wsplit<<<NTILES * DMODEL * DFF / 1024, 256>>>(up_W, uwh, uwl);
    wsplit<<<NTILES * DFF * DMODEL / 1024, 256>>>(down_W, dwh, dwl);

    // 1) LN1 (split output only)
    ln_split<false><<<NTOK, 256>>>(x, ln1_g, ln1_b, nullptr, n1h, n1l);
    // 2) QKV projection
    gemm_cp<0, false><<<dim3(D3 / 128, NTOK / 128), 512, smem_nt>>>(
        n1h, n1l, qwh, qwl, qkv_b, nullptr, qkv, nullptr, nullptr, D3, DMODEL);
    // 3) attention -> split output
    attn_mma<<<dim3(SEQ / 64, NHEAD, NB), 128, smem_attn>>>(qkv, ath, atl);
    // 4) out projection + residual
    gemm_cp<1, false><<<dim3(DMODEL / 128, NTOK / 128), 512, smem_nt>>>(
        ath, atl, owh, owl, out_b, x, xres, nullptr, nullptr, DMODEL, DMODEL);
    // 5) LN2 (fp32 + split)
    ln_split<true><<<NTOK, 256>>>(xres, ln2_g, ln2_b, n2, n2h, n2l);
    // 6) gate + bucketing
    zero_kernel<<<1, 32>>>();
    gate_kernel<<<NTOK, 256>>>(n2, gate_w, gate_b, gate_out);
    scan_kernel<<<1, 32>>>();
    scatter_kernel<<<NTOK / 256, 256>>>();
    // 7) FFN (B kept in native [K,N] layout, trans-ldmatrix)
    gemm_cp<2, true><<<dim3(DFF / 128, NTOK / 128, NTILES), 512, smem_t>>>(
        n2h, n2l, uwh, uwl, up_b, nullptr, nullptr, hh, hl, DFF, DMODEL);
    gemm_cp<3, true><<<dim3(DMODEL / 128, NTOK / 128, NTILES), 512, smem_t>>>(
        hh, hl, dwh, dwl, down_b, xres, outp, nullptr, nullptr, DMODEL, DFF);
}

// round 8
// speedup vs baseline: 1.4913x; 1.4179x over previous
#include <cuda_runtime.h>
#include <cuda_fp16.h>
#include <math.h>
#include <stdint.h>

#define NTOK 4096
#define DMODEL 1024
#define D3 3072
#define NHEAD 16
#define HDIM 64
#define SEQ 1024
#define NB 4
#define NTILES 8
#define DFF 4096

// ---------------- scratch (device globals) -------------------------------------
__device__ float g_qkv[NTOK * D3];
__device__ float g_xres[NTOK * DMODEL];
__device__ float g_n2[NTOK * DMODEL];
__device__ __half g_n1h[NTOK * DMODEL], g_n1l[NTOK * DMODEL];
__device__ __half g_attnh[NTOK * DMODEL], g_attnl[NTOK * DMODEL];
__device__ __half g_n2h[NTOK * DMODEL], g_n2l[NTOK * DMODEL];
__device__ __half g_h_hi[(size_t)NTOK * DFF], g_h_lo[(size_t)NTOK * DFF];
// single-fp16 weights (layouts preserved: qkv/out [N,K]; up/down [K,N])
__device__ __half g_qkvw[D3 * DMODEL];
__device__ __half g_outw[DMODEL * DMODEL];
__device__ __half g_upw[(size_t)NTILES * DMODEL * DFF];
__device__ __half g_dnw[(size_t)NTILES * DFF * DMODEL];
__device__ int g_tile_id[NTOK];
__device__ int g_perm[NTOK];
__device__ int g_cnt[NTILES];
__device__ int g_off[NTILES];
__device__ int g_fill[NTILES];

// ---------------- helpers -------------------------------------------------------
__device__ __forceinline__ uint32_t sptr(const void* p) {
    return (uint32_t)__cvta_generic_to_shared(p);
}
__device__ __forceinline__ uint32_t pack_h2(__half a, __half b) {
    return (uint32_t)__half_as_ushort(a) | ((uint32_t)__half_as_ushort(b) << 16);
}
// split fp32 -> fp16 hi + fp16 lo
__device__ __forceinline__ void split4_h(float4 v, __half* hi, __half* lo) {
    float a[4] = {v.x, v.y, v.z, v.w};
    __half h[4], l[4];
#pragma unroll
    for (int i = 0; i < 4; i++) {
        h[i] = __float2half_rn(a[i]);
        l[i] = __float2half_rn(a[i] - __half2float(h[i]));
    }
    *(uint32_t*)(hi)     = pack_h2(h[0], h[1]);
    *(uint32_t*)(hi + 2) = pack_h2(h[2], h[3]);
    *(uint32_t*)(lo)     = pack_h2(l[0], l[1]);
    *(uint32_t*)(lo + 2) = pack_h2(l[2], l[3]);
}
__device__ __forceinline__ void conv4_h(float4 v, __half* d) {
    *(uint32_t*)(d)     = pack_h2(__float2half_rn(v.x), __float2half_rn(v.y));
    *(uint32_t*)(d + 2) = pack_h2(__float2half_rn(v.z), __float2half_rn(v.w));
}
__device__ __forceinline__ void split2_store_h(__half* hi, __half* lo, float v0, float v1) {
    __half h0 = __float2half_rn(v0), h1 = __float2half_rn(v1);
    __half l0 = __float2half_rn(v0 - __half2float(h0));
    __half l1 = __float2half_rn(v1 - __half2float(h1));
    *(uint32_t*)hi = pack_h2(h0, h1);
    *(uint32_t*)lo = pack_h2(l0, l1);
}
__device__ __forceinline__ void split_pack_h(float x, float y, uint32_t& hi, uint32_t& lo) {
    __half hx = __float2half_rn(x), hy = __float2half_rn(y);
    __half lx = __float2half_rn(x - __half2float(hx));
    __half ly = __float2half_rn(y - __half2float(hy));
    hi = pack_h2(hx, hy);
    lo = pack_h2(lx, ly);
}
__device__ __forceinline__ void ldsm4(uint32_t* r, uint32_t a) {
    asm volatile("ldmatrix.sync.aligned.m8n8.x4.shared.b16 {%0,%1,%2,%3}, [%4];"
                 : "=r"(r[0]), "=r"(r[1]), "=r"(r[2]), "=r"(r[3]) : "r"(a));
}
__device__ __forceinline__ void ldsm4t(uint32_t* r, uint32_t a) {
    asm volatile("ldmatrix.sync.aligned.m8n8.x4.trans.shared.b16 {%0,%1,%2,%3}, [%4];"
                 : "=r"(r[0]), "=r"(r[1]), "=r"(r[2]), "=r"(r[3]) : "r"(a));
}
__device__ __forceinline__ void mma16816(float* c, const uint32_t* a, const uint32_t* b) {
    asm volatile(
        "mma.sync.aligned.m16n8k16.row.col.f32.f16.f16.f32 "
        "{%0,%1,%2,%3}, {%4,%5,%6,%7}, {%8,%9}, {%0,%1,%2,%3};"
        : "+f"(c[0]), "+f"(c[1]), "+f"(c[2]), "+f"(c[3])
        : "r"(a[0]), "r"(a[1]), "r"(a[2]), "r"(a[3]), "r"(b[0]), "r"(b[1]));
}
__device__ __forceinline__ void cpa16(uint32_t s, const void* g) {
    asm volatile("cp.async.cg.shared.global [%0], [%1], 16;" :: "r"(s), "l"(g));
}
#define CP_COMMIT() asm volatile("cp.async.commit_group;" ::: "memory")
#define CP_WAIT1() asm volatile("cp.async.wait_group 1;" ::: "memory")
#define CP_WAIT0() asm volatile("cp.async.wait_group 0;" ::: "memory")

// ---------------- weight convert (fp32 -> fp16, elementwise) ----------------------
__global__ void wconv(const float* __restrict__ src, __half* __restrict__ d) {
    size_t i = (size_t)blockIdx.x * 256 + threadIdx.x;
    float4 v = *(const float4*)(src + i * 4);
    conv4_h(v, d + i * 4);
}

// ---------------- GEMM core: one 64-K chunk, 2-pass fp16 --------------------------
// A split (hi/lo), K-major stride 72 halves. B single fp16:
//   BT=false -> K-major stride 72 (ldsm);  BT=true -> MN-major stride 136 (ldsm trans)
template <bool BT>
__device__ __forceinline__ void mma_compute(const __half* As_hi, const __half* As_lo,
                                            const __half* Bs, float (*acc)[4][4],
                                            int lane, int wm, int wn) {
#pragma unroll
    for (int s = 0; s < 4; s++) {
        const int ks = s * 16;
        uint32_t ah[2][4], al[2][4], bf[4][2];
#pragma unroll
        for (int mi = 0; mi < 2; mi++) {
            int row = wm * 32 + mi * 16 + (lane & 15);
            int col = ks + ((lane >> 4) & 1) * 8;
            ldsm4(ah[mi], sptr(As_hi + row * 72 + col));
            ldsm4(al[mi], sptr(As_lo + row * 72 + col));
        }
#pragma unroll
        for (int p = 0; p < 2; p++) {
            uint32_t r[4];
            if (!BT) {
                int n = wn * 32 + p * 16 + ((lane >> 4) & 1) * 8 + (lane & 7);
                int col = ks + ((lane >> 3) & 1) * 8;
                ldsm4(r, sptr(Bs + n * 72 + col));
            } else {
                int k = ks + ((lane >> 3) & 1) * 8 + (lane & 7);
                int n = wn * 32 + p * 16 + ((lane >> 4) & 1) * 8;
                ldsm4t(r, sptr(Bs + k * 136 + n));
            }
            bf[2 * p][0] = r[0]; bf[2 * p][1] = r[1];
            bf[2 * p + 1][0] = r[2]; bf[2 * p + 1][1] = r[3];
        }
#pragma unroll
        for (int mi = 0; mi < 2; mi++)
#pragma unroll
            for (int ni = 0; ni < 4; ni++) {
                mma16816(acc[mi][ni], ah[mi], bf[ni]);
                mma16816(acc[mi][ni], al[mi], bf[ni]);
            }
    }
}

// ---------------- GEMM: C[M,N] = A[M,K] * B^T, 512 thr, 3-stage cp.async ----------
// MODE 0: +bias -> fp32 C          MODE 1: +bias +resid -> fp32 C
// MODE 2: gather A rows via perm, +bias, relu -> split Oh/Ol (compact), BT
// MODE 3: A compact (off+row), +bias +resid, scatter -> fp32 C, BT
// stage bytes: Ah[128*144] @0, Al @18432, B @36864 (NT: 128*144 / T: 64*272)
#define ABYTES 18432
#define BOFF 36864
#define STG_NT 55296
#define STG_T 54272

template <int MODE, bool BT>
__global__ __launch_bounds__(512, 1) void gemm_cp(
    const __half* __restrict__ Ah, const __half* __restrict__ Al,
    const __half* __restrict__ W, const float* __restrict__ bias,
    const float* __restrict__ resid, float* __restrict__ C,
    __half* __restrict__ Oh, __half* __restrict__ Ol, int N, int K) {
    constexpr int STG = BT ? STG_T : STG_NT;
    extern __shared__ __half dsm[];
    const int tid = threadIdx.x, lane = tid & 31, w = tid >> 5;
    const int wm = w & 3, wn = w >> 2;
    const int bn = blockIdx.x * 128, bm = blockIdx.y * 128;
    int cnt = 0, off = 0;
    if (MODE >= 2) {
        const int t = blockIdx.z;
        cnt = g_cnt[t];
        if (bm >= cnt) return;
        off = g_off[t];
        W += (size_t)t * N * K;
        bias += (size_t)t * N;
    }
    const uint32_t sb = sptr(dsm);
    // A fill roles: rows ar0, ar0+64; 8-half chunk kc
    const int ar0 = tid >> 3, kc = tid & 7;
    const uint32_t adst0 = (uint32_t)(ar0 * 144 + kc * 16);
    const uint32_t adst1 = (uint32_t)((ar0 + 64) * 144 + kc * 16);
    size_t abase0, abase1;
    if (MODE <= 1) {
        abase0 = (size_t)(bm + ar0) * K;
        abase1 = (size_t)(bm + ar0 + 64) * K;
    } else if (MODE == 2) {
        int t0 = (bm + ar0 < cnt) ? g_perm[off + bm + ar0] : 0;
        int t1 = (bm + ar0 + 64 < cnt) ? g_perm[off + bm + ar0 + 64] : 0;
        abase0 = (size_t)t0 * K;
        abase1 = (size_t)t1 * K;
    } else {
        int r0c = (bm + ar0 < cnt) ? bm + ar0 : 0;
        int r1c = (bm + ar0 + 64 < cnt) ? bm + ar0 + 64 : 0;
        abase0 = (size_t)(off + r0c) * K;
        abase1 = (size_t)(off + r1c) * K;
    }
    // B fill roles
    size_t bb0 = 0, bb1 = 0;
    uint32_t bd0 = 0, bd1 = 0;
    int bkc = 0, btr = 0, btc = 0;
    if (!BT) {
        bb0 = (size_t)(bn + ar0) * K;
        bb1 = (size_t)(bn + ar0 + 64) * K;
        bd0 = BOFF + adst0;
        bd1 = BOFF + adst1;
        bkc = kc;
    } else {
        btr = tid >> 4;          // k row 0..31
        btc = tid & 15;          // 8-half chunk along n
        bd0 = (uint32_t)(BOFF + btr * 272 + btc * 16);
        bd1 = (uint32_t)(BOFF + (btr + 32) * 272 + btc * 16);
    }
    const int NC = K >> 6;
    auto fill = [&](int s, int c) {
        const int k0 = c * 64;
        const uint32_t st = sb + s * STG;
        cpa16(st + adst0,          Ah + abase0 + k0 + kc * 8);
        cpa16(st + ABYTES + adst0, Al + abase0 + k0 + kc * 8);
        cpa16(st + adst1,          Ah + abase1 + k0 + kc * 8);
        cpa16(st + ABYTES + adst1, Al + abase1 + k0 + kc * 8);
        if (!BT) {
            cpa16(st + bd0, W + bb0 + k0 + bkc * 8);
            cpa16(st + bd1, W + bb1 + k0 + bkc * 8);
        } else {
            cpa16(st + bd0, W + (size_t)(k0 + btr) * N + bn + btc * 8);
            cpa16(st + bd1, W + (size_t)(k0 + btr + 32) * N + bn + btc * 8);
        }
        CP_COMMIT();
    };
    fill(0, 0);
    if (NC > 1) fill(1, 1);
    float acc[2][4][4] = {};
    int sidx = 0;
    for (int c = 0; c < NC; c++) {
        if (c + 2 < NC) CP_WAIT1(); else CP_WAIT0();
        __syncthreads();
        if (c + 2 < NC) fill((sidx + 2) % 3, c + 2);
        const __half* b0 = dsm + sidx * (STG / 2);
        mma_compute<BT>(b0, b0 + ABYTES / 2, b0 + BOFF / 2, acc, lane, wm, wn);
        sidx = (sidx + 1) % 3;
        __syncthreads();
    }
    // ---- epilogue
#pragma unroll
    for (int mi = 0; mi < 2; mi++) {
        int r0 = bm + wm * 32 + mi * 16 + (lane >> 2);
#pragma unroll
        for (int ni = 0; ni < 4; ni++) {
            int cn = bn + wn * 32 + ni * 8 + (lane & 3) * 2;
            float2 bs = *(const float2*)(bias + cn);
            if (MODE <= 1) {
                float2 o0 = make_float2(acc[mi][ni][0] + bs.x, acc[mi][ni][1] + bs.y);
                float2 o1 = make_float2(acc[mi][ni][2] + bs.x, acc[mi][ni][3] + bs.y);
                if (MODE == 1) {
                    float2 ra = *(const float2*)(resid + (size_t)r0 * N + cn);
                    float2 rb = *(const float2*)(resid + (size_t)(r0 + 8) * N + cn);
                    o0.x += ra.x; o0.y += ra.y; o1.x += rb.x; o1.y += rb.y;
                }
                *(float2*)(C + (size_t)r0 * N + cn) = o0;
                *(float2*)(C + (size_t)(r0 + 8) * N + cn) = o1;
            } else if (MODE == 2) {
                if (r0 < cnt) {
                    float v0 = fmaxf(acc[mi][ni][0] + bs.x, 0.f);
                    float v1 = fmaxf(acc[mi][ni][1] + bs.y, 0.f);
                    split2_store_h(Oh + (size_t)(off + r0) * N + cn,
                                   Ol + (size_t)(off + r0) * N + cn, v0, v1);
                }
                if (r0 + 8 < cnt) {
                    float v2 = fmaxf(acc[mi][ni][2] + bs.x, 0.f);
                    float v3 = fmaxf(acc[mi][ni][3] + bs.y, 0.f);
                    split2_store_h(Oh + (size_t)(off + r0 + 8) * N + cn,
                                   Ol + (size_t)(off + r0 + 8) * N + cn, v2, v3);
                }
            } else {  // MODE 3
                if (r0 < cnt) {
                    int tok = g_perm[off + r0];
                    float2 xr = *(const float2*)(resid + (size_t)tok * N + cn);
                    *(float2*)(C + (size_t)tok * N + cn) =
                        make_float2(acc[mi][ni][0] + bs.x + xr.x, acc[mi][ni][1] + bs.y + xr.y);
                }
                if (r0 + 8 < cnt) {
                    int tok = g_perm[off + r0 + 8];
                    float2 xr = *(const float2*)(resid + (size_t)tok * N + cn);
                    *(float2*)(C + (size_t)tok * N + cn) =
                        make_float2(acc[mi][ni][2] + bs.x + xr.x, acc[mi][ni][3] + bs.y + xr.y);
                }
            }
        }
    }
}

// ---------------- layernorm with split fp16 output ---------------------------------
template <bool FP32OUT>
__global__ void ln_split(const float* __restrict__ x, const float* __restrict__ g,
                         const float* __restrict__ bb, float* __restrict__ y,
                         __half* __restrict__ yh, __half* __restrict__ yl) {
    int t = blockIdx.x;
    const float* xr = x + (size_t)t * DMODEL;
    int d = threadIdx.x * 4;
    float4 v = *(const float4*)(xr + d);
    float s = v.x + v.y + v.z + v.w;
    float s2 = v.x * v.x + v.y * v.y + v.z * v.z + v.w * v.w;
#pragma unroll
    for (int o = 16; o; o >>= 1) {
        s += __shfl_xor_sync(0xffffffffu, s, o);
        s2 += __shfl_xor_sync(0xffffffffu, s2, o);
    }
    __shared__ float rs[8], rq[8];
    if ((threadIdx.x & 31) == 0) { rs[threadIdx.x >> 5] = s; rq[threadIdx.x >> 5] = s2; }
    __syncthreads();
    __shared__ float smean, srstd;
    if (threadIdx.x == 0) {
        float a = 0.f, b2 = 0.f;
#pragma unroll
        for (int i = 0; i < 8; i++) { a += rs[i]; b2 += rq[i]; }
        float mean = a * (1.f / DMODEL);
        float var = b2 * (1.f / DMODEL) - mean * mean;
        smean = mean; srstd = rsqrtf(var + 1e-5f);
    }
    __syncthreads();
    float mean = smean, rstd = srstd;
    float4 gv = *(const float4*)(g + d);
    float4 bv = *(const float4*)(bb + d);
    float4 o;
    o.x = (v.x - mean) * rstd * gv.x + bv.x;
    o.y = (v.y - mean) * rstd * gv.y + bv.y;
    o.z = (v.z - mean) * rstd * gv.z + bv.z;
    o.w = (v.w - mean) * rstd * gv.w + bv.w;
    if (FP32OUT) *(float4*)(y + (size_t)t * DMODEL + d) = o;
    split4_h(o, yh + (size_t)t * DMODEL + d, yl + (size_t)t * DMODEL + d);
}

// ---------------- MMA flash attention (fp16 2-pass, split output) ------------------
__global__ __launch_bounds__(128) void attn_mma(const float* __restrict__ qkv,
                                                __half* __restrict__ oh,
                                                __half* __restrict__ ol) {
    __shared__ __half smem[18432];  // Qh,Ql,K,V each 64x72
    __half* Qh = smem;
    __half* Ql = smem + 4608;
    __half* Ks = smem + 9216;
    __half* Vs = smem + 13824;

    const int qt = blockIdx.x, h = blockIdx.y, b = blockIdx.z;
    const int tid = threadIdx.x, lane = tid & 31, wid = tid >> 5;
    const int tok0 = b * SEQ + qt * 64;
    const int wq = wid * 16;

    // Q: 64 rows x 64 cols; 512 slots of 8 values; scale + split
#pragma unroll
    for (int i = 0; i < 4; i++) {
        int idx = i * 128 + tid;
        int row = idx >> 3, c8 = (idx & 7) * 8;
        const float* src = qkv + (size_t)(tok0 + row) * D3 + h * HDIM + c8;
        float4 v0 = *(const float4*)(src);
        float4 v1 = *(const float4*)(src + 4);
        v0.x *= 0.125f; v0.y *= 0.125f; v0.z *= 0.125f; v0.w *= 0.125f;
        v1.x *= 0.125f; v1.y *= 0.125f; v1.z *= 0.125f; v1.w *= 0.125f;
        split4_h(v0, Qh + row * 72 + c8, Ql + row * 72 + c8);
        split4_h(v1, Qh + row * 72 + c8 + 4, Ql + row * 72 + c8 + 4);
    }

    float m_[2] = {-1e30f, -1e30f}, l_[2] = {0.f, 0.f};
    float O[8][4] = {};

    for (int kt = 0; kt < 16; kt++) {
        int kb = b * SEQ + kt * 64;
        __syncthreads();
#pragma unroll
        for (int i = 0; i < 4; i++) {
            int idx = i * 128 + tid;
            int row = idx >> 3, c8 = (idx & 7) * 8;
            const float* base = qkv + (size_t)(kb + row) * D3 + h * HDIM + c8;
            float4 k0 = *(const float4*)(base + DMODEL);
            float4 k1 = *(const float4*)(base + DMODEL + 4);
            conv4_h(k0, Ks + row * 72 + c8);
            conv4_h(k1, Ks + row * 72 + c8 + 4);
            float4 w0 = *(const float4*)(base + 2 * DMODEL);
            float4 w1 = *(const float4*)(base + 2 * DMODEL + 4);
            conv4_h(w0, Vs + row * 72 + c8);
            conv4_h(w1, Vs + row * 72 + c8 + 4);
        }
        __syncthreads();

        float S[8][4] = {};
#pragma unroll
        for (int ks = 0; ks < 4; ks++) {
            uint32_t qh[4], ql[4], kf[8][2];
            {
                int row = wq + (lane & 15);
                int col = ks * 16 + ((lane >> 4) & 1) * 8;
                ldsm4(qh, sptr(Qh + row * 72 + col));
                ldsm4(ql, sptr(Ql + row * 72 + col));
            }
#pragma unroll
            for (int p = 0; p < 4; p++) {
                uint32_t r[4];
                int n = p * 16 + ((lane >> 4) & 1) * 8 + (lane & 7);
                int col = ks * 16 + ((lane >> 3) & 1) * 8;
                ldsm4(r, sptr(Ks + n * 72 + col));
                kf[2 * p][0] = r[0]; kf[2 * p][1] = r[1];
                kf[2 * p + 1][0] = r[2]; kf[2 * p + 1][1] = r[3];
            }
#pragma unroll
            for (int j = 0; j < 8; j++) {
                mma16816(S[j], qh, kf[j]);
                mma16816(S[j], ql, kf[j]);
            }
        }

        float fac[2];
#pragma unroll
        for (int h2 = 0; h2 < 2; h2++) {
            float rm = -1e30f;
#pragma unroll
            for (int j = 0; j < 8; j++)
                rm = fmaxf(rm, fmaxf(S[j][2 * h2], S[j][2 * h2 + 1]));
            rm = fmaxf(rm, __shfl_xor_sync(0xffffffffu, rm, 1));
            rm = fmaxf(rm, __shfl_xor_sync(0xffffffffu, rm, 2));
            float mn = fmaxf(m_[h2], rm);
            fac[h2] = __expf(m_[h2] - mn);
            float rsum = 0.f;
#pragma unroll
            for (int j = 0; j < 8; j++) {
                float p0 = __expf(S[j][2 * h2] - mn);
                float p1 = __expf(S[j][2 * h2 + 1] - mn);
                S[j][2 * h2] = p0; S[j][2 * h2 + 1] = p1;
                rsum += p0 + p1;
            }
            rsum += __shfl_xor_sync(0xffffffffu, rsum, 1);
            rsum += __shfl_xor_sync(0xffffffffu, rsum, 2);
            l_[h2] = l_[h2] * fac[h2] + rsum;
            m_[h2] = mn;
        }
#pragma unroll
        for (int j = 0; j < 8; j++) {
            O[j][0] *= fac[0]; O[j][1] *= fac[0];
            O[j][2] *= fac[1]; O[j][3] *= fac[1];
        }

#pragma unroll
        for (int ks = 0; ks < 4; ks++) {
            uint32_t ph[4], pl[4];
            split_pack_h(S[2 * ks][0], S[2 * ks][1], ph[0], pl[0]);
            split_pack_h(S[2 * ks][2], S[2 * ks][3], ph[1], pl[1]);
            split_pack_h(S[2 * ks + 1][0], S[2 * ks + 1][1], ph[2], pl[2]);
            split_pack_h(S[2 * ks + 1][2], S[2 * ks + 1][3], ph[3], pl[3]);
            uint32_t vf[8][2];
#pragma unroll
            for (int p = 0; p < 4; p++) {
                uint32_t r[4];
                int k = ks * 16 + ((lane >> 3) & 1) * 8 + (lane & 7);
                int n = p * 16 + ((lane >> 4) & 1) * 8;
                ldsm4t(r, sptr(Vs + k * 72 + n));
                vf[2 * p][0] = r[0]; vf[2 * p][1] = r[1];
                vf[2 * p + 1][0] = r[2]; vf[2 * p + 1][1] = r[3];
            }
#pragma unroll
            for (int j = 0; j < 8; j++) {
                mma16816(O[j], ph, vf[j]);
                mma16816(O[j], pl, vf[j]);
            }
        }
    }

    float inv0 = 1.f / l_[0], inv1 = 1.f / l_[1];
    int r0 = tok0 + wq + (lane >> 2);
#pragma unroll
    for (int j = 0; j < 8; j++) {
        int col = h * HDIM + j * 8 + (lane & 3) * 2;
        split2_store_h(oh + (size_t)r0 * DMODEL + col, ol + (size_t)r0 * DMODEL + col,
                       O[j][0] * inv0, O[j][1] * inv0);
        split2_store_h(oh + (size_t)(r0 + 8) * DMODEL + col, ol + (size_t)(r0 + 8) * DMODEL + col,
                       O[j][2] * inv1, O[j][3] * inv1);
    }
}

// ---------------- gate / bucketing -------------------------------------------------
__global__ void zero_kernel() {
    if (threadIdx.x < NTILES) { g_cnt[threadIdx.x] = 0; g_fill[threadIdx.x] = 0; }
}

__global__ void gate_kernel(const float* __restrict__ n2, const float* __restrict__ gw,
                            const float* __restrict__ gb, float* __restrict__ gate_out) {
    int t = blockIdx.x;
    const float* xr = n2 + (size_t)t * DMODEL;
    float lg[NTILES] = {};
    for (int d = threadIdx.x; d < DMODEL; d += 256) {
        float v = xr[d];
#pragma unroll
        for (int e = 0; e < NTILES; e++) lg[e] += v * gw[e * DMODEL + d];
    }
#pragma unroll
    for (int o = 16; o; o >>= 1)
#pragma unroll
        for (int e = 0; e < NTILES; e++) lg[e] += __shfl_xor_sync(0xffffffffu, lg[e], o);
    __shared__ float smv[8][NTILES];
    if ((threadIdx.x & 31) == 0)
#pragma unroll
        for (int e = 0; e < NTILES; e++) smv[threadIdx.x >> 5][e] = lg[e];
    __syncthreads();
    if (threadIdx.x == 0) {
        int best = 0; float bv = -1e30f;
#pragma unroll
        for (int e = 0; e < NTILES; e++) {
            float v = gb[e];
#pragma unroll
            for (int w = 0; w < 8; w++) v += smv[w][e];
            if (v > bv) { bv = v; best = e; }
        }
        g_tile_id[t] = best;
#pragma unroll
        for (int e = 0; e < NTILES; e++) gate_out[(size_t)t * NTILES + e] = (e == best) ? 1.f : 0.f;
        atomicAdd(&g_cnt[best], 1);
    }
}

__global__ void scan_kernel() {
    if (threadIdx.x == 0) {
        int a = 0;
        for (int e = 0; e < NTILES; e++) { g_off[e] = a; a += g_cnt[e]; }
    }
}

__global__ void scatter_kernel() {
    int t = blockIdx.x * 256 + threadIdx.x;
    int e = g_tile_id[t];
    int p = atomicAdd(&g_fill[e], 1);
    g_perm[g_off[e] + p] = t;
}

// ---------------- launch ------------------------------------------------------------
extern "C" void kernel_launch(void* const* d_in, const int* in_sizes, int n_in,
                              void* d_out, int out_size) {
    const float* x      = (const float*)d_in[0];
    const float* ln1_g  = (const float*)d_in[1];
    const float* ln1_b  = (const float*)d_in[2];
    const float* qkv_w  = (const float*)d_in[3];
    const float* qkv_b  = (const float*)d_in[4];
    const float* out_w  = (const float*)d_in[5];
    const float* out_b  = (const float*)d_in[6];
    const float* ln2_g  = (const float*)d_in[7];
    const float* ln2_b  = (const float*)d_in[8];
    const float* gate_w = (const float*)d_in[9];
    const float* gate_b = (const float*)d_in[10];
    const float* up_W   = (const float*)d_in[11];
    const float* up_b   = (const float*)d_in[12];
    const float* down_W = (const float*)d_in[13];
    const float* down_b = (const float*)d_in[14];

    float* outp = (float*)d_out;
    float* gate_out = outp + (size_t)NTOK * DMODEL;

    void* p;
    cudaGetSymbolAddress(&p, g_qkv);   float* qkv  = (float*)p;
    cudaGetSymbolAddress(&p, g_xres);  float* xres = (float*)p;
    cudaGetSymbolAddress(&p, g_n2);    float* n2   = (float*)p;
    cudaGetSymbolAddress(&p, g_n1h);   __half* n1h = (__half*)p;
    cudaGetSymbolAddress(&p, g_n1l);   __half* n1l = (__half*)p;
    cudaGetSymbolAddress(&p, g_attnh); __half* ath = (__half*)p;
    cudaGetSymbolAddress(&p, g_attnl); __half* atl = (__half*)p;
    cudaGetSymbolAddress(&p, g_n2h);   __half* n2h = (__half*)p;
    cudaGetSymbolAddress(&p, g_n2l);   __half* n2l = (__half*)p;
    cudaGetSymbolAddress(&p, g_h_hi);  __half* hh = (__half*)p;
    cudaGetSymbolAddress(&p, g_h_lo);  __half* hl = (__half*)p;
    cudaGetSymbolAddress(&p, g_qkvw);  __half* qw = (__half*)p;
    cudaGetSymbolAddress(&p, g_outw);  __half* ow = (__half*)p;
    cudaGetSymbolAddress(&p, g_upw);   __half* uw = (__half*)p;
    cudaGetSymbolAddress(&p, g_dnw);   __half* dw = (__half*)p;

    const int smem_nt = 3 * STG_NT;  // 165888
    const int smem_t  = 3 * STG_T;   // 162816
    cudaFuncSetAttribute(gemm_cp<0, false>, cudaFuncAttributeMaxDynamicSharedMemorySize, smem_nt);
    cudaFuncSetAttribute(gemm_cp<1, false>, cudaFuncAttributeMaxDynamicSharedMemorySize, smem_nt);
    cudaFuncSetAttribute(gemm_cp<2, true>, cudaFuncAttributeMaxDynamicSharedMemorySize, smem_t);
    cudaFuncSetAttribute(gemm_cp<3, true>, cudaFuncAttributeMaxDynamicSharedMemorySize, smem_t);

    // 0) weight convert (fp32 -> fp16, single array each)
    wconv<<<D3 * DMODEL / 1024, 256>>>(qkv_w, qw);
    wconv<<<DMODEL * DMODEL / 1024, 256>>>(out_w, ow);
    wconv<<<NTILES * DMODEL * DFF / 1024, 256>>>(up_W, uw);
    wconv<<<NTILES * DFF * DMODEL / 1024, 256>>>(down_W, dw);

    // 1) LN1 (split fp16 output)
    ln_split<false><<<NTOK, 256>>>(x, ln1_g, ln1_b, nullptr, n1h, n1l);
    // 2) QKV projection
    gemm_cp<0, false><<<dim3(D3 / 128, NTOK / 128), 512, smem_nt>>>(
        n1h, n1l, qw, qkv_b, nullptr, qkv, nullptr, nullptr, D3, DMODEL);
    // 3) attention
    attn_mma<<<dim3(SEQ / 64, NHEAD, NB), 128>>>(qkv, ath, atl);
    // 4) out projection + residual
    gemm_cp<1, false><<<dim3(DMODEL / 128, NTOK / 128), 512, smem_nt>>>(
        ath, atl, ow, out_b, x, xres, nullptr, nullptr, DMODEL, DMODEL);
    // 5) LN2 (fp32 + split)
    ln_split<true><<<NTOK, 256>>>(xres, ln2_g, ln2_b, n2, n2h, n2l);
    // 6) gate + bucketing
    zero_kernel<<<1, 32>>>();
    gate_kernel<<<NTOK, 256>>>(n2, gate_w, gate_b, gate_out);
    scan_kernel<<<1, 32>>>();
    scatter_kernel<<<NTOK / 256, 256>>>();
    // 7) FFN (B native [K,N], trans-ldmatrix)
    gemm_cp<2, true><<<dim3(DFF / 128, NTOK / 128, NTILES), 512, smem_t>>>(
        n2h, n2l, uw, up_b, nullptr, nullptr, hh, hl, DFF, DMODEL);
    gemm_cp<3, true><<<dim3(DMODEL / 128, NTOK / 128, NTILES), 512, smem_t>>>(
        hh, hl, dw, down_b, xres, outp, nullptr, nullptr, DMODEL, DFF);
}

// round 9
// speedup vs baseline: 1.9681x; 1.3197x over previous
#include <cuda_runtime.h>
#include <cuda_fp16.h>
#include <math.h>
#include <stdint.h>

#define NTOK 4096
#define DMODEL 1024
#define D3 3072
#define NHEAD 16
#define HDIM 64
#define SEQ 1024
#define NB 4
#define NTILES 8
#define DFF 4096

// ---------------- scratch (device globals) -------------------------------------
__device__ float g_qkv[NTOK * D3];
__device__ float g_xres[NTOK * DMODEL];
__device__ float g_n2[NTOK * DMODEL];
__device__ __half g_n1[NTOK * DMODEL];
__device__ __half g_attn[NTOK * DMODEL];
__device__ __half g_n2x[NTOK * DMODEL];
__device__ __half g_h[(size_t)NTOK * DFF];
// single-fp16 weights (layouts preserved: qkv/out [N,K]; up/down [K,N])
__device__ __half g_qkvw[D3 * DMODEL];
__device__ __half g_outw[DMODEL * DMODEL];
__device__ __half g_upw[(size_t)NTILES * DMODEL * DFF];
__device__ __half g_dnw[(size_t)NTILES * DFF * DMODEL];
__device__ int g_tile_id[NTOK];
__device__ int g_perm[NTOK];
__device__ int g_cnt[NTILES];
__device__ int g_off[NTILES];
__device__ int g_fill[NTILES];

// ---------------- helpers -------------------------------------------------------
__device__ __forceinline__ uint32_t sptr(const void* p) {
    return (uint32_t)__cvta_generic_to_shared(p);
}
__device__ __forceinline__ uint32_t pack_h2(__half a, __half b) {
    return (uint32_t)__half_as_ushort(a) | ((uint32_t)__half_as_ushort(b) << 16);
}
__device__ __forceinline__ void conv4_h(float4 v, __half* d) {
    *(uint32_t*)(d)     = pack_h2(__float2half_rn(v.x), __float2half_rn(v.y));
    *(uint32_t*)(d + 2) = pack_h2(__float2half_rn(v.z), __float2half_rn(v.w));
}
// split fp32 -> fp16 hi + fp16 lo (attention only)
__device__ __forceinline__ void split4_h(float4 v, __half* hi, __half* lo) {
    float a[4] = {v.x, v.y, v.z, v.w};
    __half h[4], l[4];
#pragma unroll
    for (int i = 0; i < 4; i++) {
        h[i] = __float2half_rn(a[i]);
        l[i] = __float2half_rn(a[i] - __half2float(h[i]));
    }
    *(uint32_t*)(hi)     = pack_h2(h[0], h[1]);
    *(uint32_t*)(hi + 2) = pack_h2(h[2], h[3]);
    *(uint32_t*)(lo)     = pack_h2(l[0], l[1]);
    *(uint32_t*)(lo + 2) = pack_h2(l[2], l[3]);
}
__device__ __forceinline__ void split_pack_h(float x, float y, uint32_t& hi, uint32_t& lo) {
    __half hx = __float2half_rn(x), hy = __float2half_rn(y);
    __half lx = __float2half_rn(x - __half2float(hx));
    __half ly = __float2half_rn(y - __half2float(hy));
    hi = pack_h2(hx, hy);
    lo = pack_h2(lx, ly);
}
__device__ __forceinline__ void ldsm4(uint32_t* r, uint32_t a) {
    asm volatile("ldmatrix.sync.aligned.m8n8.x4.shared.b16 {%0,%1,%2,%3}, [%4];"
                 : "=r"(r[0]), "=r"(r[1]), "=r"(r[2]), "=r"(r[3]) : "r"(a));
}
__device__ __forceinline__ void ldsm4t(uint32_t* r, uint32_t a) {
    asm volatile("ldmatrix.sync.aligned.m8n8.x4.trans.shared.b16 {%0,%1,%2,%3}, [%4];"
                 : "=r"(r[0]), "=r"(r[1]), "=r"(r[2]), "=r"(r[3]) : "r"(a));
}
__device__ __forceinline__ void mma16816(float* c, const uint32_t* a, const uint32_t* b) {
    asm volatile(
        "mma.sync.aligned.m16n8k16.row.col.f32.f16.f16.f32 "
        "{%0,%1,%2,%3}, {%4,%5,%6,%7}, {%8,%9}, {%0,%1,%2,%3};"
        : "+f"(c[0]), "+f"(c[1]), "+f"(c[2]), "+f"(c[3])
        : "r"(a[0]), "r"(a[1]), "r"(a[2]), "r"(a[3]), "r"(b[0]), "r"(b[1]));
}
__device__ __forceinline__ void cpa16(uint32_t s, const void* g) {
    asm volatile("cp.async.cg.shared.global [%0], [%1], 16;" :: "r"(s), "l"(g));
}
#define CP_COMMIT() asm volatile("cp.async.commit_group;" ::: "memory")
#define CP_WAIT2() asm volatile("cp.async.wait_group 2;" ::: "memory")
#define CP_WAIT0() asm volatile("cp.async.wait_group 0;" ::: "memory")

// ---------------- weight convert (fp32 -> fp16, elementwise) ----------------------
__global__ void wconv(const float* __restrict__ src, __half* __restrict__ d) {
    size_t i = (size_t)blockIdx.x * 256 + threadIdx.x;
    float4 v = *(const float4*)(src + i * 4);
    conv4_h(v, d + i * 4);
}

// ---------------- GEMM core: one 64-K chunk, single-pass fp16 ---------------------
// A K-major stride 72 halves. B: BT=false K-major stride 72 (ldsm);
// BT=true MN-major stride 136 (ldsm trans).
template <bool BT>
__device__ __forceinline__ void mma_compute(const __half* As, const __half* Bs,
                                            float (*acc)[4][4], int lane, int wm, int wn) {
#pragma unroll
    for (int s = 0; s < 4; s++) {
        const int ks = s * 16;
        uint32_t af[2][4], bf[4][2];
#pragma unroll
        for (int mi = 0; mi < 2; mi++) {
            int row = wm * 32 + mi * 16 + (lane & 15);
            int col = ks + ((lane >> 4) & 1) * 8;
            ldsm4(af[mi], sptr(As + row * 72 + col));
        }
#pragma unroll
        for (int p = 0; p < 2; p++) {
            uint32_t r[4];
            if (!BT) {
                int n = wn * 32 + p * 16 + ((lane >> 4) & 1) * 8 + (lane & 7);
                int col = ks + ((lane >> 3) & 1) * 8;
                ldsm4(r, sptr(Bs + n * 72 + col));
            } else {
                int k = ks + ((lane >> 3) & 1) * 8 + (lane & 7);
                int n = wn * 32 + p * 16 + ((lane >> 4) & 1) * 8;
                ldsm4t(r, sptr(Bs + k * 136 + n));
            }
            bf[2 * p][0] = r[0]; bf[2 * p][1] = r[1];
            bf[2 * p + 1][0] = r[2]; bf[2 * p + 1][1] = r[3];
        }
#pragma unroll
        for (int mi = 0; mi < 2; mi++)
#pragma unroll
            for (int ni = 0; ni < 4; ni++)
                mma16816(acc[mi][ni], af[mi], bf[ni]);
    }
}

// ---------------- GEMM: C[M,N] = A[M,K] * B^T, 512 thr, 4-stage cp.async ----------
// MODE 0: +bias -> fp32 C          MODE 1: +bias +resid -> fp32 C
// MODE 2: gather A via perm, +bias, relu -> fp16 O (compact), BT
// MODE 3: A compact (off+row), +bias +resid, scatter -> fp32 C, BT
// stage: A[128*144B] @0, B @18432 (NT: 128*144B / T: 64*272B)
#define BOFF 18432
#define STG_NT 36864
#define STG_T 35840

template <int MODE, bool BT>
__global__ __launch_bounds__(512, 1) void gemm_cp(
    const __half* __restrict__ Ah, const __half* __restrict__ W,
    const float* __restrict__ bias, const float* __restrict__ resid,
    float* __restrict__ C, __half* __restrict__ O, int N, int K) {
    constexpr int STG = BT ? STG_T : STG_NT;
    extern __shared__ __half dsm[];
    const int tid = threadIdx.x, lane = tid & 31, w = tid >> 5;
    const int wm = w & 3, wn = w >> 2;
    const int bn = blockIdx.x * 128, bm = blockIdx.y * 128;
    int cnt = 0, off = 0;
    if (MODE >= 2) {
        const int t = blockIdx.z;
        cnt = g_cnt[t];
        if (bm >= cnt) return;
        off = g_off[t];
        W += (size_t)t * N * K;
        bias += (size_t)t * N;
    }
    const uint32_t sb = sptr(dsm);
    // A fill roles: rows ar0, ar0+64; 8-half chunk kc
    const int ar0 = tid >> 3, kc = tid & 7;
    const uint32_t adst0 = (uint32_t)(ar0 * 144 + kc * 16);
    const uint32_t adst1 = (uint32_t)((ar0 + 64) * 144 + kc * 16);
    size_t abase0, abase1;
    if (MODE <= 1) {
        abase0 = (size_t)(bm + ar0) * K;
        abase1 = (size_t)(bm + ar0 + 64) * K;
    } else if (MODE == 2) {
        int t0 = (bm + ar0 < cnt) ? g_perm[off + bm + ar0] : 0;
        int t1 = (bm + ar0 + 64 < cnt) ? g_perm[off + bm + ar0 + 64] : 0;
        abase0 = (size_t)t0 * K;
        abase1 = (size_t)t1 * K;
    } else {
        int r0c = (bm + ar0 < cnt) ? bm + ar0 : 0;
        int r1c = (bm + ar0 + 64 < cnt) ? bm + ar0 + 64 : 0;
        abase0 = (size_t)(off + r0c) * K;
        abase1 = (size_t)(off + r1c) * K;
    }
    // B fill roles
    size_t bb0 = 0, bb1 = 0;
    uint32_t bd0 = 0, bd1 = 0;
    int bkc = 0, btr = 0, btc = 0;
    if (!BT) {
        bb0 = (size_t)(bn + ar0) * K;
        bb1 = (size_t)(bn + ar0 + 64) * K;
        bd0 = BOFF + adst0;
        bd1 = BOFF + adst1;
        bkc = kc;
    } else {
        btr = tid >> 4;          // k row 0..31
        btc = tid & 15;          // 8-half chunk along n
        bd0 = (uint32_t)(BOFF + btr * 272 + btc * 16);
        bd1 = (uint32_t)(BOFF + (btr + 32) * 272 + btc * 16);
    }
    const int NC = K >> 6;
    auto fill = [&](int s, int c) {
        const int k0 = c * 64;
        const uint32_t st = sb + s * STG;
        cpa16(st + adst0, Ah + abase0 + k0 + kc * 8);
        cpa16(st + adst1, Ah + abase1 + k0 + kc * 8);
        if (!BT) {
            cpa16(st + bd0, W + bb0 + k0 + bkc * 8);
            cpa16(st + bd1, W + bb1 + k0 + bkc * 8);
        } else {
            cpa16(st + bd0, W + (size_t)(k0 + btr) * N + bn + btc * 8);
            cpa16(st + bd1, W + (size_t)(k0 + btr + 32) * N + bn + btc * 8);
        }
        CP_COMMIT();
    };
    fill(0, 0);
    if (NC > 1) fill(1, 1);
    if (NC > 2) fill(2, 2);
    float acc[2][4][4] = {};
    for (int c = 0; c < NC; c++) {
        if (c + 3 < NC) CP_WAIT2(); else CP_WAIT0();
        __syncthreads();  // makes fills visible AND guards stage reuse
        if (c + 3 < NC) fill((c + 3) & 3, c + 3);
        const __half* b0 = dsm + (c & 3) * (STG / 2);
        mma_compute<BT>(b0, b0 + BOFF / 2, acc, lane, wm, wn);
        __syncthreads();  // reads done before next fill targets this stage
    }
    // ---- epilogue
#pragma unroll
    for (int mi = 0; mi < 2; mi++) {
        int r0 = bm + wm * 32 + mi * 16 + (lane >> 2);
#pragma unroll
        for (int ni = 0; ni < 4; ni++) {
            int cn = bn + wn * 32 + ni * 8 + (lane & 3) * 2;
            float2 bs = *(const float2*)(bias + cn);
            if (MODE <= 1) {
                float2 o0 = make_float2(acc[mi][ni][0] + bs.x, acc[mi][ni][1] + bs.y);
                float2 o1 = make_float2(acc[mi][ni][2] + bs.x, acc[mi][ni][3] + bs.y);
                if (MODE == 1) {
                    float2 ra = *(const float2*)(resid + (size_t)r0 * N + cn);
                    float2 rb = *(const float2*)(resid + (size_t)(r0 + 8) * N + cn);
                    o0.x += ra.x; o0.y += ra.y; o1.x += rb.x; o1.y += rb.y;
                }
                *(float2*)(C + (size_t)r0 * N + cn) = o0;
                *(float2*)(C + (size_t)(r0 + 8) * N + cn) = o1;
            } else if (MODE == 2) {
                if (r0 < cnt) {
                    float v0 = fmaxf(acc[mi][ni][0] + bs.x, 0.f);
                    float v1 = fmaxf(acc[mi][ni][1] + bs.y, 0.f);
                    *(uint32_t*)(O + (size_t)(off + r0) * N + cn) =
                        pack_h2(__float2half_rn(v0), __float2half_rn(v1));
                }
                if (r0 + 8 < cnt) {
                    float v2 = fmaxf(acc[mi][ni][2] + bs.x, 0.f);
                    float v3 = fmaxf(acc[mi][ni][3] + bs.y, 0.f);
                    *(uint32_t*)(O + (size_t)(off + r0 + 8) * N + cn) =
                        pack_h2(__float2half_rn(v2), __float2half_rn(v3));
                }
            } else {  // MODE 3
                if (r0 < cnt) {
                    int tok = g_perm[off + r0];
                    float2 xr = *(const float2*)(resid + (size_t)tok * N + cn);
                    *(float2*)(C + (size_t)tok * N + cn) =
                        make_float2(acc[mi][ni][0] + bs.x + xr.x, acc[mi][ni][1] + bs.y + xr.y);
                }
                if (r0 + 8 < cnt) {
                    int tok = g_perm[off + r0 + 8];
                    float2 xr = *(const float2*)(resid + (size_t)tok * N + cn);
                    *(float2*)(C + (size_t)tok * N + cn) =
                        make_float2(acc[mi][ni][2] + bs.x + xr.x, acc[mi][ni][3] + bs.y + xr.y);
                }
            }
        }
    }
}

// ---------------- layernorm with fp16 output ---------------------------------------
template <bool FP32OUT>
__global__ void ln_conv(const float* __restrict__ x, const float* __restrict__ g,
                        const float* __restrict__ bb, float* __restrict__ y,
                        __half* __restrict__ yh) {
    int t = blockIdx.x;
    const float* xr = x + (size_t)t * DMODEL;
    int d = threadIdx.x * 4;
    float4 v = *(const float4*)(xr + d);
    float s = v.x + v.y + v.z + v.w;
    float s2 = v.x * v.x + v.y * v.y + v.z * v.z + v.w * v.w;
#pragma unroll
    for (int o = 16; o; o >>= 1) {
        s += __shfl_xor_sync(0xffffffffu, s, o);
        s2 += __shfl_xor_sync(0xffffffffu, s2, o);
    }
    __shared__ float rs[8], rq[8];
    if ((threadIdx.x & 31) == 0) { rs[threadIdx.x >> 5] = s; rq[threadIdx.x >> 5] = s2; }
    __syncthreads();
    __shared__ float smean, srstd;
    if (threadIdx.x == 0) {
        float a = 0.f, b2 = 0.f;
#pragma unroll
        for (int i = 0; i < 8; i++) { a += rs[i]; b2 += rq[i]; }
        float mean = a * (1.f / DMODEL);
        float var = b2 * (1.f / DMODEL) - mean * mean;
        smean = mean; srstd = rsqrtf(var + 1e-5f);
    }
    __syncthreads();
    float mean = smean, rstd = srstd;
    float4 gv = *(const float4*)(g + d);
    float4 bv = *(const float4*)(bb + d);
    float4 o;
    o.x = (v.x - mean) * rstd * gv.x + bv.x;
    o.y = (v.y - mean) * rstd * gv.y + bv.y;
    o.z = (v.z - mean) * rstd * gv.z + bv.z;
    o.w = (v.w - mean) * rstd * gv.w + bv.w;
    if (FP32OUT) *(float4*)(y + (size_t)t * DMODEL + d) = o;
    conv4_h(o, yh + (size_t)t * DMODEL + d);
}

// ---------------- MMA flash attention (fp16, Q/P 2-pass; fp16 out) -----------------
__global__ __launch_bounds__(128) void attn_mma(const float* __restrict__ qkv,
                                                __half* __restrict__ oh) {
    __shared__ __half smem[18432];  // Qh,Ql,K,V each 64x72
    __half* Qh = smem;
    __half* Ql = smem + 4608;
    __half* Ks = smem + 9216;
    __half* Vs = smem + 13824;

    const int qt = blockIdx.x, h = blockIdx.y, b = blockIdx.z;
    const int tid = threadIdx.x, lane = tid & 31, wid = tid >> 5;
    const int tok0 = b * SEQ + qt * 64;
    const int wq = wid * 16;

#pragma unroll
    for (int i = 0; i < 4; i++) {
        int idx = i * 128 + tid;
        int row = idx >> 3, c8 = (idx & 7) * 8;
        const float* src = qkv + (size_t)(tok0 + row) * D3 + h * HDIM + c8;
        float4 v0 = *(const float4*)(src);
        float4 v1 = *(const float4*)(src + 4);
        v0.x *= 0.125f; v0.y *= 0.125f; v0.z *= 0.125f; v0.w *= 0.125f;
        v1.x *= 0.125f; v1.y *= 0.125f; v1.z *= 0.125f; v1.w *= 0.125f;
        split4_h(v0, Qh + row * 72 + c8, Ql + row * 72 + c8);
        split4_h(v1, Qh + row * 72 + c8 + 4, Ql + row * 72 + c8 + 4);
    }

    float m_[2] = {-1e30f, -1e30f}, l_[2] = {0.f, 0.f};
    float O[8][4] = {};

    for (int kt = 0; kt < 16; kt++) {
        int kb = b * SEQ + kt * 64;
        __syncthreads();
#pragma unroll
        for (int i = 0; i < 4; i++) {
            int idx = i * 128 + tid;
            int row = idx >> 3, c8 = (idx & 7) * 8;
            const float* base = qkv + (size_t)(kb + row) * D3 + h * HDIM + c8;
            float4 k0 = *(const float4*)(base + DMODEL);
            float4 k1 = *(const float4*)(base + DMODEL + 4);
            conv4_h(k0, Ks + row * 72 + c8);
            conv4_h(k1, Ks + row * 72 + c8 + 4);
            float4 w0 = *(const float4*)(base + 2 * DMODEL);
            float4 w1 = *(const float4*)(base + 2 * DMODEL + 4);
            conv4_h(w0, Vs + row * 72 + c8);
            conv4_h(w1, Vs + row * 72 + c8 + 4);
        }
        __syncthreads();

        float S[8][4] = {};
#pragma unroll
        for (int ks = 0; ks < 4; ks++) {
            uint32_t qh[4], ql[4], kf[8][2];
            {
                int row = wq + (lane & 15);
                int col = ks * 16 + ((lane >> 4) & 1) * 8;
                ldsm4(qh, sptr(Qh + row * 72 + col));
                ldsm4(ql, sptr(Ql + row * 72 + col));
            }
#pragma unroll
            for (int p = 0; p < 4; p++) {
                uint32_t r[4];
                int n = p * 16 + ((lane >> 4) & 1) * 8 + (lane & 7);
                int col = ks * 16 + ((lane >> 3) & 1) * 8;
                ldsm4(r, sptr(Ks + n * 72 + col));
                kf[2 * p][0] = r[0]; kf[2 * p][1] = r[1];
                kf[2 * p + 1][0] = r[2]; kf[2 * p + 1][1] = r[3];
            }
#pragma unroll
            for (int j = 0; j < 8; j++) {
                mma16816(S[j], qh, kf[j]);
                mma16816(S[j], ql, kf[j]);
            }
        }

        float fac[2];
#pragma unroll
        for (int h2 = 0; h2 < 2; h2++) {
            float rm = -1e30f;
#pragma unroll
            for (int j = 0; j < 8; j++)
                rm = fmaxf(rm, fmaxf(S[j][2 * h2], S[j][2 * h2 + 1]));
            rm = fmaxf(rm, __shfl_xor_sync(0xffffffffu, rm, 1));
            rm = fmaxf(rm, __shfl_xor_sync(0xffffffffu, rm, 2));
            float mn = fmaxf(m_[h2], rm);
            fac[h2] = __expf(m_[h2] - mn);
            float rsum = 0.f;
#pragma unroll
            for (int j = 0; j < 8; j++) {
                float p0 = __expf(S[j][2 * h2] - mn);
                float p1 = __expf(S[j][2 * h2 + 1] - mn);
                S[j][2 * h2] = p0; S[j][2 * h2 + 1] = p1;
                rsum += p0 + p1;
            }
            rsum += __shfl_xor_sync(0xffffffffu, rsum, 1);
            rsum += __shfl_xor_sync(0xffffffffu, rsum, 2);
            l_[h2] = l_[h2] * fac[h2] + rsum;
            m_[h2] = mn;
        }
#pragma unroll
        for (int j = 0; j < 8; j++) {
            O[j][0] *= fac[0]; O[j][1] *= fac[0];
            O[j][2] *= fac[1]; O[j][3] *= fac[1];
        }

#pragma unroll
        for (int ks = 0; ks < 4; ks++) {
            uint32_t ph[4], pl[4];
            split_pack_h(S[2 * ks][0], S[2 * ks][1], ph[0], pl[0]);
            split_pack_h(S[2 * ks][2], S[2 * ks][3], ph[1], pl[1]);
            split_pack_h(S[2 * ks + 1][0], S[2 * ks + 1][1], ph[2], pl[2]);
            split_pack_h(S[2 * ks + 1][2], S[2 * ks + 1][3], ph[3], pl[3]);
            uint32_t vf[8][2];
#pragma unroll
            for (int p = 0; p < 4; p++) {
                uint32_t r[4];
                int k = ks * 16 + ((lane >> 3) & 1) * 8 + (lane & 7);
                int n = p * 16 + ((lane >> 4) & 1) * 8;
                ldsm4t(r, sptr(Vs + k * 72 + n));
                vf[2 * p][0] = r[0]; vf[2 * p][1] = r[1];
                vf[2 * p + 1][0] = r[2]; vf[2 * p + 1][1] = r[3];
            }
#pragma unroll
            for (int j = 0; j < 8; j++) {
                mma16816(O[j], ph, vf[j]);
                mma16816(O[j], pl, vf[j]);
            }
        }
    }

    float inv0 = 1.f / l_[0], inv1 = 1.f / l_[1];
    int r0 = tok0 + wq + (lane >> 2);
#pragma unroll
    for (int j = 0; j < 8; j++) {
        int col = h * HDIM + j * 8 + (lane & 3) * 2;
        *(uint32_t*)(oh + (size_t)r0 * DMODEL + col) =
            pack_h2(__float2half_rn(O[j][0] * inv0), __float2half_rn(O[j][1] * inv0));
        *(uint32_t*)(oh + (size_t)(r0 + 8) * DMODEL + col) =
            pack_h2(__float2half_rn(O[j][2] * inv1), __float2half_rn(O[j][3] * inv1));
    }
}

// ---------------- gate / bucketing -------------------------------------------------
__global__ void zero_kernel() {
    if (threadIdx.x < NTILES) { g_cnt[threadIdx.x] = 0; g_fill[threadIdx.x] = 0; }
}

__global__ void gate_kernel(const float* __restrict__ n2, const float* __restrict__ gw,
                            const float* __restrict__ gb, float* __restrict__ gate_out) {
    int t = blockIdx.x;
    const float* xr = n2 + (size_t)t * DMODEL;
    float lg[NTILES] = {};
    for (int d = threadIdx.x; d < DMODEL; d += 256) {
        float v = xr[d];
#pragma unroll
        for (int e = 0; e < NTILES; e++) lg[e] += v * gw[e * DMODEL + d];
    }
#pragma unroll
    for (int o = 16; o; o >>= 1)
#pragma unroll
        for (int e = 0; e < NTILES; e++) lg[e] += __shfl_xor_sync(0xffffffffu, lg[e], o);
    __shared__ float smv[8][NTILES];
    if ((threadIdx.x & 31) == 0)
#pragma unroll
        for (int e = 0; e < NTILES; e++) smv[threadIdx.x >> 5][e] = lg[e];
    __syncthreads();
    if (threadIdx.x == 0) {
        int best = 0; float bv = -1e30f;
#pragma unroll
        for (int e = 0; e < NTILES; e++) {
            float v = gb[e];
#pragma unroll
            for (int w = 0; w < 8; w++) v += smv[w][e];
            if (v > bv) { bv = v; best = e; }
        }
        g_tile_id[t] = best;
#pragma unroll
        for (int e = 0; e < NTILES; e++) gate_out[(size_t)t * NTILES + e] = (e == best) ? 1.f : 0.f;
        atomicAdd(&g_cnt[best], 1);
    }
}

__global__ void scan_kernel() {
    if (threadIdx.x == 0) {
        int a = 0;
        for (int e = 0; e < NTILES; e++) { g_off[e] = a; a += g_cnt[e]; }
    }
}

__global__ void scatter_kernel() {
    int t = blockIdx.x * 256 + threadIdx.x;
    int e = g_tile_id[t];
    int p = atomicAdd(&g_fill[e], 1);
    g_perm[g_off[e] + p] = t;
}

// ---------------- launch ------------------------------------------------------------
extern "C" void kernel_launch(void* const* d_in, const int* in_sizes, int n_in,
                              void* d_out, int out_size) {
    const float* x      = (const float*)d_in[0];
    const float* ln1_g  = (const float*)d_in[1];
    const float* ln1_b  = (const float*)d_in[2];
    const float* qkv_w  = (const float*)d_in[3];
    const float* qkv_b  = (const float*)d_in[4];
    const float* out_w  = (const float*)d_in[5];
    const float* out_b  = (const float*)d_in[6];
    const float* ln2_g  = (const float*)d_in[7];
    const float* ln2_b  = (const float*)d_in[8];
    const float* gate_w = (const float*)d_in[9];
    const float* gate_b = (const float*)d_in[10];
    const float* up_W   = (const float*)d_in[11];
    const float* up_b   = (const float*)d_in[12];
    const float* down_W = (const float*)d_in[13];
    const float* down_b = (const float*)d_in[14];

    float* outp = (float*)d_out;
    float* gate_out = outp + (size_t)NTOK * DMODEL;

    void* p;
    cudaGetSymbolAddress(&p, g_qkv);  float* qkv  = (float*)p;
    cudaGetSymbolAddress(&p, g_xres); float* xres = (float*)p;
    cudaGetSymbolAddress(&p, g_n2);   float* n2   = (float*)p;
    cudaGetSymbolAddress(&p, g_n1);   __half* n1h = (__half*)p;
    cudaGetSymbolAddress(&p, g_attn); __half* ath = (__half*)p;
    cudaGetSymbolAddress(&p, g_n2x);  __half* n2h = (__half*)p;
    cudaGetSymbolAddress(&p, g_h);    __half* hh = (__half*)p;
    cudaGetSymbolAddress(&p, g_qkvw); __half* qw = (__half*)p;
    cudaGetSymbolAddress(&p, g_outw); __half* ow = (__half*)p;
    cudaGetSymbolAddress(&p, g_upw);  __half* uw = (__half*)p;
    cudaGetSymbolAddress(&p, g_dnw);  __half* dw = (__half*)p;

    const int smem_nt = 4 * STG_NT;  // 147456
    const int smem_t  = 4 * STG_T;   // 143360
    cudaFuncSetAttribute(gemm_cp<0, false>, cudaFuncAttributeMaxDynamicSharedMemorySize, smem_nt);
    cudaFuncSetAttribute(gemm_cp<1, false>, cudaFuncAttributeMaxDynamicSharedMemorySize, smem_nt);
    cudaFuncSetAttribute(gemm_cp<2, true>, cudaFuncAttributeMaxDynamicSharedMemorySize, smem_t);
    cudaFuncSetAttribute(gemm_cp<3, true>, cudaFuncAttributeMaxDynamicSharedMemorySize, smem_t);

    // 0) weight convert (fp32 -> fp16)
    wconv<<<D3 * DMODEL / 1024, 256>>>(qkv_w, qw);
    wconv<<<DMODEL * DMODEL / 1024, 256>>>(out_w, ow);
    wconv<<<NTILES * DMODEL * DFF / 1024, 256>>>(up_W, uw);
    wconv<<<NTILES * DFF * DMODEL / 1024, 256>>>(down_W, dw);

    // 1) LN1 (fp16 output)
    ln_conv<false><<<NTOK, 256>>>(x, ln1_g, ln1_b, nullptr, n1h);
    // 2) QKV projection
    gemm_cp<0, false><<<dim3(D3 / 128, NTOK / 128), 512, smem_nt>>>(
        n1h, qw, qkv_b, nullptr, qkv, nullptr, D3, DMODEL);
    // 3) attention
    attn_mma<<<dim3(SEQ / 64, NHEAD, NB), 128>>>(qkv, ath);
    // 4) out projection + residual
    gemm_cp<1, false><<<dim3(DMODEL / 128, NTOK / 128), 512, smem_nt>>>(
        ath, ow, out_b, x, xres, nullptr, DMODEL, DMODEL);
    // 5) LN2 (fp32 + fp16)
    ln_conv<true><<<NTOK, 256>>>(xres, ln2_g, ln2_b, n2, n2h);
    // 6) gate + bucketing
    zero_kernel<<<1, 32>>>();
    gate_kernel<<<NTOK, 256>>>(n2, gate_w, gate_b, gate_out);
    scan_kernel<<<1, 32>>>();
    scatter_kernel<<<NTOK / 256, 256>>>();
    // 7) FFN (B native [K,N], trans-ldmatrix)
    gemm_cp<2, true><<<dim3(DFF / 128, NTOK / 128, NTILES), 512, smem_t>>>(
        n2h, uw, up_b, nullptr, nullptr, hh, DFF, DMODEL);
    gemm_cp<3, true><<<dim3(DMODEL / 128, NTOK / 128, NTILES), 512, smem_t>>>(
        hh, dw, down_b, xres, outp, nullptr, DMODEL, DFF);
}

// round 11
// speedup vs baseline: 2.0359x; 1.0345x over previous
#include <cuda_runtime.h>
#include <cuda_fp16.h>
#include <math.h>
#include <stdint.h>

#define NTOK 4096
#define DMODEL 1024
#define D3 3072
#define NHEAD 16
#define HDIM 64
#define SEQ 1024
#define NB 4
#define NTILES 8
#define DFF 4096

// ---------------- scratch (device globals) -------------------------------------
__device__ __half g_qkv[NTOK * D3];          // fp16 QKV output
__device__ float g_xres[NTOK * DMODEL];
__device__ float g_n2[NTOK * DMODEL];
__device__ __half g_n1[NTOK * DMODEL];
__device__ __half g_attn[NTOK * DMODEL];
__device__ __half g_n2x[NTOK * DMODEL];
__device__ __half g_h[(size_t)NTOK * DFF];
__device__ __half g_qkvw[D3 * DMODEL];
__device__ __half g_outw[DMODEL * DMODEL];
__device__ __half g_upw[(size_t)NTILES * DMODEL * DFF];
__device__ __half g_dnw[(size_t)NTILES * DFF * DMODEL];
__device__ int g_tile_id[NTOK];
__device__ int g_perm[NTOK];
__device__ int g_cnt[NTILES];
__device__ int g_off[NTILES];
__device__ int g_fill[NTILES];

// ---------------- helpers -------------------------------------------------------
__device__ __forceinline__ uint32_t sptr(const void* p) {
    return (uint32_t)__cvta_generic_to_shared(p);
}
__device__ __forceinline__ uint32_t pack_h2(__half a, __half b) {
    return (uint32_t)__half_as_ushort(a) | ((uint32_t)__half_as_ushort(b) << 16);
}
__device__ __forceinline__ void conv4_h(float4 v, __half* d) {
    *(uint32_t*)(d)     = pack_h2(__float2half_rn(v.x), __float2half_rn(v.y));
    *(uint32_t*)(d + 2) = pack_h2(__float2half_rn(v.z), __float2half_rn(v.w));
}
__device__ __forceinline__ void split_pack_h(float x, float y, uint32_t& hi, uint32_t& lo) {
    __half hx = __float2half_rn(x), hy = __float2half_rn(y);
    __half lx = __float2half_rn(x - __half2float(hx));
    __half ly = __float2half_rn(y - __half2float(hy));
    hi = pack_h2(hx, hy);
    lo = pack_h2(lx, ly);
}
__device__ __forceinline__ void ldsm4(uint32_t* r, uint32_t a) {
    asm volatile("ldmatrix.sync.aligned.m8n8.x4.shared.b16 {%0,%1,%2,%3}, [%4];"
                 : "=r"(r[0]), "=r"(r[1]), "=r"(r[2]), "=r"(r[3]) : "r"(a));
}
__device__ __forceinline__ void ldsm4t(uint32_t* r, uint32_t a) {
    asm volatile("ldmatrix.sync.aligned.m8n8.x4.trans.shared.b16 {%0,%1,%2,%3}, [%4];"
                 : "=r"(r[0]), "=r"(r[1]), "=r"(r[2]), "=r"(r[3]) : "r"(a));
}
__device__ __forceinline__ void mma16816(float* c, const uint32_t* a, const uint32_t* b) {
    asm volatile(
        "mma.sync.aligned.m16n8k16.row.col.f32.f16.f16.f32 "
        "{%0,%1,%2,%3}, {%4,%5,%6,%7}, {%8,%9}, {%0,%1,%2,%3};"
        : "+f"(c[0]), "+f"(c[1]), "+f"(c[2]), "+f"(c[3])
        : "r"(a[0]), "r"(a[1]), "r"(a[2]), "r"(a[3]), "r"(b[0]), "r"(b[1]));
}
__device__ __forceinline__ void cpa16(uint32_t s, const void* g) {
    asm volatile("cp.async.cg.shared.global [%0], [%1], 16;" :: "r"(s), "l"(g));
}
#define CP_COMMIT() asm volatile("cp.async.commit_group;" ::: "memory")
#define CP_WAIT2() asm volatile("cp.async.wait_group 2;" ::: "memory")
#define CP_WAIT0() asm volatile("cp.async.wait_group 0;" ::: "memory")

// ---------------- weight convert (fp32 -> fp16, elementwise) ----------------------
__global__ void wconv(const float* __restrict__ src, __half* __restrict__ d) {
    size_t i = (size_t)blockIdx.x * 256 + threadIdx.x;
    float4 v = *(const float4*)(src + i * 4);
    conv4_h(v, d + i * 4);
}

// ---------------- GEMM core: one 64-K chunk, single-pass fp16 ---------------------
template <bool BT>
__device__ __forceinline__ void mma_compute(const __half* As, const __half* Bs,
                                            float (*acc)[4][4], int lane, int wm, int wn) {
#pragma unroll
    for (int s = 0; s < 4; s++) {
        const int ks = s * 16;
        uint32_t af[2][4], bf[4][2];
#pragma unroll
        for (int mi = 0; mi < 2; mi++) {
            int row = wm * 32 + mi * 16 + (lane & 15);
            int col = ks + ((lane >> 4) & 1) * 8;
            ldsm4(af[mi], sptr(As + row * 72 + col));
        }
#pragma unroll
        for (int p = 0; p < 2; p++) {
            uint32_t r[4];
            if (!BT) {
                int n = wn * 32 + p * 16 + ((lane >> 4) & 1) * 8 + (lane & 7);
                int col = ks + ((lane >> 3) & 1) * 8;
                ldsm4(r, sptr(Bs + n * 72 + col));
            } else {
                int k = ks + ((lane >> 3) & 1) * 8 + (lane & 7);
                int n = wn * 32 + p * 16 + ((lane >> 4) & 1) * 8;
                ldsm4t(r, sptr(Bs + k * 136 + n));
            }
            bf[2 * p][0] = r[0]; bf[2 * p][1] = r[1];
            bf[2 * p + 1][0] = r[2]; bf[2 * p + 1][1] = r[3];
        }
#pragma unroll
        for (int mi = 0; mi < 2; mi++)
#pragma unroll
            for (int ni = 0; ni < 4; ni++)
                mma16816(acc[mi][ni], af[mi], bf[ni]);
    }
}

// ---------------- GEMM: C = A * B^T, 512 thr, 4-stage cp.async, 1 barrier/chunk ----
// MODE 0: +bias -> fp16 O          MODE 1: +bias +resid -> fp32 C
// MODE 2: gather A via perm, +bias, relu -> fp16 O (compact), BT
// MODE 3: A compact, +bias +resid, scatter -> fp32 C, BT
#define BOFF 18432
#define STG_NT 36864
#define STG_T 35840

template <int MODE, bool BT>
__global__ __launch_bounds__(512, 1) void gemm_cp(
    const __half* __restrict__ Ah, const __half* __restrict__ W,
    const float* __restrict__ bias, const float* __restrict__ resid,
    float* __restrict__ C, __half* __restrict__ O, int N, int K) {
    constexpr int STG = BT ? STG_T : STG_NT;
    extern __shared__ __half dsm[];
    const int tid = threadIdx.x, lane = tid & 31, w = tid >> 5;
    const int wm = w & 3, wn = w >> 2;
    const int bn = blockIdx.x * 128, bm = blockIdx.y * 128;
    int cnt = 0, off = 0;
    if (MODE >= 2) {
        const int t = blockIdx.z;
        cnt = g_cnt[t];
        if (bm >= cnt) return;
        off = g_off[t];
        W += (size_t)t * N * K;
        bias += (size_t)t * N;
    }
    const uint32_t sb = sptr(dsm);
    const int ar0 = tid >> 3, kc = tid & 7;
    const uint32_t adst0 = (uint32_t)(ar0 * 144 + kc * 16);
    const uint32_t adst1 = (uint32_t)((ar0 + 64) * 144 + kc * 16);
    size_t abase0, abase1;
    if (MODE <= 1) {
        abase0 = (size_t)(bm + ar0) * K;
        abase1 = (size_t)(bm + ar0 + 64) * K;
    } else if (MODE == 2) {
        int t0 = (bm + ar0 < cnt) ? g_perm[off + bm + ar0] : 0;
        int t1 = (bm + ar0 + 64 < cnt) ? g_perm[off + bm + ar0 + 64] : 0;
        abase0 = (size_t)t0 * K;
        abase1 = (size_t)t1 * K;
    } else {
        int r0c = (bm + ar0 < cnt) ? bm + ar0 : 0;
        int r1c = (bm + ar0 + 64 < cnt) ? bm + ar0 + 64 : 0;
        abase0 = (size_t)(off + r0c) * K;
        abase1 = (size_t)(off + r1c) * K;
    }
    size_t bb0 = 0, bb1 = 0;
    uint32_t bd0 = 0, bd1 = 0;
    int bkc = 0, btr = 0, btc = 0;
    if (!BT) {
        bb0 = (size_t)(bn + ar0) * K;
        bb1 = (size_t)(bn + ar0 + 64) * K;
        bd0 = BOFF + adst0;
        bd1 = BOFF + adst1;
        bkc = kc;
    } else {
        btr = tid >> 4;
        btc = tid & 15;
        bd0 = (uint32_t)(BOFF + btr * 272 + btc * 16);
        bd1 = (uint32_t)(BOFF + (btr + 32) * 272 + btc * 16);
    }
    const int NC = K >> 6;
    auto fill = [&](int s, int c) {
        const int k0 = c * 64;
        const uint32_t st = sb + s * STG;
        cpa16(st + adst0, Ah + abase0 + k0 + kc * 8);
        cpa16(st + adst1, Ah + abase1 + k0 + kc * 8);
        if (!BT) {
            cpa16(st + bd0, W + bb0 + k0 + bkc * 8);
            cpa16(st + bd1, W + bb1 + k0 + bkc * 8);
        } else {
            cpa16(st + bd0, W + (size_t)(k0 + btr) * N + bn + btc * 8);
            cpa16(st + bd1, W + (size_t)(k0 + btr + 32) * N + bn + btc * 8);
        }
        CP_COMMIT();
    };
    fill(0, 0);
    if (NC > 1) fill(1, 1);
    if (NC > 2) fill(2, 2);
    float acc[2][4][4] = {};
    for (int c = 0; c < NC; c++) {
        if (c + 3 < NC) CP_WAIT2(); else CP_WAIT0();
        __syncthreads();  // data visible; all warps past chunk c-1's reads
        if (c + 3 < NC) fill((c + 3) & 3, c + 3);  // targets stage (c-1)&3: safe
        const __half* b0 = dsm + (c & 3) * (STG / 2);
        mma_compute<BT>(b0, b0 + BOFF / 2, acc, lane, wm, wn);
    }
    // ---- epilogue
#pragma unroll
    for (int mi = 0; mi < 2; mi++) {
        int r0 = bm + wm * 32 + mi * 16 + (lane >> 2);
#pragma unroll
        for (int ni = 0; ni < 4; ni++) {
            int cn = bn + wn * 32 + ni * 8 + (lane & 3) * 2;
            float2 bs = *(const float2*)(bias + cn);
            if (MODE == 0) {
                *(uint32_t*)(O + (size_t)r0 * N + cn) =
                    pack_h2(__float2half_rn(acc[mi][ni][0] + bs.x),
                            __float2half_rn(acc[mi][ni][1] + bs.y));
                *(uint32_t*)(O + (size_t)(r0 + 8) * N + cn) =
                    pack_h2(__float2half_rn(acc[mi][ni][2] + bs.x),
                            __float2half_rn(acc[mi][ni][3] + bs.y));
            } else if (MODE == 1) {
                float2 ra = *(const float2*)(resid + (size_t)r0 * N + cn);
                float2 rb = *(const float2*)(resid + (size_t)(r0 + 8) * N + cn);
                *(float2*)(C + (size_t)r0 * N + cn) =
                    make_float2(acc[mi][ni][0] + bs.x + ra.x, acc[mi][ni][1] + bs.y + ra.y);
                *(float2*)(C + (size_t)(r0 + 8) * N + cn) =
                    make_float2(acc[mi][ni][2] + bs.x + rb.x, acc[mi][ni][3] + bs.y + rb.y);
            } else if (MODE == 2) {
                if (r0 < cnt) {
                    float v0 = fmaxf(acc[mi][ni][0] + bs.x, 0.f);
                    float v1 = fmaxf(acc[mi][ni][1] + bs.y, 0.f);
                    *(uint32_t*)(O + (size_t)(off + r0) * N + cn) =
                        pack_h2(__float2half_rn(v0), __float2half_rn(v1));
                }
                if (r0 + 8 < cnt) {
                    float v2 = fmaxf(acc[mi][ni][2] + bs.x, 0.f);
                    float v3 = fmaxf(acc[mi][ni][3] + bs.y, 0.f);
                    *(uint32_t*)(O + (size_t)(off + r0 + 8) * N + cn) =
                        pack_h2(__float2half_rn(v2), __float2half_rn(v3));
                }
            } else {
                if (r0 < cnt) {
                    int tok = g_perm[off + r0];
                    float2 xr = *(const float2*)(resid + (size_t)tok * N + cn);
                    *(float2*)(C + (size_t)tok * N + cn) =
                        make_float2(acc[mi][ni][0] + bs.x + xr.x, acc[mi][ni][1] + bs.y + xr.y);
                }
                if (r0 + 8 < cnt) {
                    int tok = g_perm[off + r0 + 8];
                    float2 xr = *(const float2*)(resid + (size_t)tok * N + cn);
                    *(float2*)(C + (size_t)tok * N + cn) =
                        make_float2(acc[mi][ni][2] + bs.x + xr.x, acc[mi][ni][3] + bs.y + xr.y);
                }
            }
        }
    }
}

// ---------------- layernorm with fp16 output ---------------------------------------
template <bool FP32OUT>
__global__ void ln_conv(const float* __restrict__ x, const float* __restrict__ g,
                        const float* __restrict__ bb, float* __restrict__ y,
                        __half* __restrict__ yh) {
    int t = blockIdx.x;
    const float* xr = x + (size_t)t * DMODEL;
    int d = threadIdx.x * 4;
    float4 v = *(const float4*)(xr + d);
    float s = v.x + v.y + v.z + v.w;
    float s2 = v.x * v.x + v.y * v.y + v.z * v.z + v.w * v.w;
#pragma unroll
    for (int o = 16; o; o >>= 1) {
        s += __shfl_xor_sync(0xffffffffu, s, o);
        s2 += __shfl_xor_sync(0xffffffffu, s2, o);
    }
    __shared__ float rs[8], rq[8];
    if ((threadIdx.x & 31) == 0) { rs[threadIdx.x >> 5] = s; rq[threadIdx.x >> 5] = s2; }
    __syncthreads();
    __shared__ float smean, srstd;
    if (threadIdx.x == 0) {
        float a = 0.f, b2 = 0.f;
#pragma unroll
        for (int i = 0; i < 8; i++) { a += rs[i]; b2 += rq[i]; }
        float mean = a * (1.f / DMODEL);
        float var = b2 * (1.f / DMODEL) - mean * mean;
        smean = mean; srstd = rsqrtf(var + 1e-5f);
    }
    __syncthreads();
    float mean = smean, rstd = srstd;
    float4 gv = *(const float4*)(g + d);
    float4 bv = *(const float4*)(bb + d);
    float4 o;
    o.x = (v.x - mean) * rstd * gv.x + bv.x;
    o.y = (v.y - mean) * rstd * gv.y + bv.y;
    o.z = (v.z - mean) * rstd * gv.z + bv.z;
    o.w = (v.w - mean) * rstd * gv.w + bv.w;
    if (FP32OUT) *(float4*)(y + (size_t)t * DMODEL + d) = o;
    conv4_h(o, yh + (size_t)t * DMODEL + d);
}

// ---------------- flash attention: fp16 QKV in, pure cp.async, double-buffered K/V -
// S = Q*K (1 pass, scaled post-MMA); P*V 2-pass compensated.
// Loader: 128 threads; thread -> row tid>>1, column half (tid&1)*32 halves = 4x16B.
__global__ __launch_bounds__(128) void attn_mma(const __half* __restrict__ qkv,
                                                __half* __restrict__ oh) {
    __shared__ __half smem[64 * 72 * 5];  // Q + K[2] + V[2]
    __half* Qs = smem;
    __half* Kb[2] = {smem + 4608, smem + 9216};
    __half* Vb[2] = {smem + 13824, smem + 18432};

    const int qt = blockIdx.x, h = blockIdx.y, b = blockIdx.z;
    const int tid = threadIdx.x, lane = tid & 31, wid = tid >> 5;
    const int tok0 = b * SEQ + qt * 64;
    const int wq = wid * 16;
    const int lrow = tid >> 1, lcb = (tid & 1) * 32;  // row, column base (halves)

    // Q load: 4 x 16B per thread (joins group 0 with kt=0 K/V)
    {
        const __half* src = qkv + (size_t)(tok0 + lrow) * D3 + h * HDIM + lcb;
        uint32_t qd = sptr(Qs + lrow * 72 + lcb);
#pragma unroll
        for (int i = 0; i < 4; i++) cpa16(qd + i * 16, src + i * 8);
    }
    auto fill_kv = [&](int buf, int kt) {
        const __half* base = qkv + (size_t)(b * SEQ + kt * 64 + lrow) * D3 + h * HDIM + lcb;
        uint32_t kd = sptr(Kb[buf] + lrow * 72 + lcb);
        uint32_t vd = sptr(Vb[buf] + lrow * 72 + lcb);
#pragma unroll
        for (int i = 0; i < 4; i++) {
            cpa16(kd + i * 16, base + DMODEL + i * 8);
            cpa16(vd + i * 16, base + 2 * DMODEL + i * 8);
        }
        CP_COMMIT();
    };
    fill_kv(0, 0);

    float m_[2] = {-1e30f, -1e30f}, l_[2] = {0.f, 0.f};
    float O[8][4] = {};
    int buf = 0;

    for (int kt = 0; kt < 16; kt++) {
        CP_WAIT0();
        __syncthreads();
        if (kt + 1 < 16) fill_kv(buf ^ 1, kt + 1);
        const __half* Ks = Kb[buf];
        const __half* Vs = Vb[buf];

        float S[8][4] = {};
#pragma unroll
        for (int ks = 0; ks < 4; ks++) {
            uint32_t qf[4], kf[8][2];
            {
                int row = wq + (lane & 15);
                int col = ks * 16 + ((lane >> 4) & 1) * 8;
                ldsm4(qf, sptr(Qs + row * 72 + col));
            }
#pragma unroll
            for (int p = 0; p < 4; p++) {
                uint32_t r[4];
                int n = p * 16 + ((lane >> 4) & 1) * 8 + (lane & 7);
                int col = ks * 16 + ((lane >> 3) & 1) * 8;
                ldsm4(r, sptr(Ks + n * 72 + col));
                kf[2 * p][0] = r[0]; kf[2 * p][1] = r[1];
                kf[2 * p + 1][0] = r[2]; kf[2 * p + 1][1] = r[3];
            }
#pragma unroll
            for (int j = 0; j < 8; j++) mma16816(S[j], qf, kf[j]);
        }

        float fac[2];
#pragma unroll
        for (int h2 = 0; h2 < 2; h2++) {
            float rm = -1e30f;
#pragma unroll
            for (int j = 0; j < 8; j++) {
                S[j][2 * h2] *= 0.125f;
                S[j][2 * h2 + 1] *= 0.125f;
                rm = fmaxf(rm, fmaxf(S[j][2 * h2], S[j][2 * h2 + 1]));
            }
            rm = fmaxf(rm, __shfl_xor_sync(0xffffffffu, rm, 1));
            rm = fmaxf(rm, __shfl_xor_sync(0xffffffffu, rm, 2));
            float mn = fmaxf(m_[h2], rm);
            fac[h2] = __expf(m_[h2] - mn);
            float rsum = 0.f;
#pragma unroll
            for (int j = 0; j < 8; j++) {
                float p0 = __expf(S[j][2 * h2] - mn);
                float p1 = __expf(S[j][2 * h2 + 1] - mn);
                S[j][2 * h2] = p0; S[j][2 * h2 + 1] = p1;
                rsum += p0 + p1;
            }
            rsum += __shfl_xor_sync(0xffffffffu, rsum, 1);
            rsum += __shfl_xor_sync(0xffffffffu, rsum, 2);
            l_[h2] = l_[h2] * fac[h2] + rsum;
            m_[h2] = mn;
        }
#pragma unroll
        for (int j = 0; j < 8; j++) {
            O[j][0] *= fac[0]; O[j][1] *= fac[0];
            O[j][2] *= fac[1]; O[j][3] *= fac[1];
        }

#pragma unroll
        for (int ks = 0; ks < 4; ks++) {
            uint32_t ph[4], pl[4];
            split_pack_h(S[2 * ks][0], S[2 * ks][1], ph[0], pl[0]);
            split_pack_h(S[2 * ks][2], S[2 * ks][3], ph[1], pl[1]);
            split_pack_h(S[2 * ks + 1][0], S[2 * ks + 1][1], ph[2], pl[2]);
            split_pack_h(S[2 * ks + 1][2], S[2 * ks + 1][3], ph[3], pl[3]);
            uint32_t vf[8][2];
#pragma unroll
            for (int p = 0; p < 4; p++) {
                uint32_t r[4];
                int k = ks * 16 + ((lane >> 3) & 1) * 8 + (lane & 7);
                int n = p * 16 + ((lane >> 4) & 1) * 8;
                ldsm4t(r, sptr(Vs + k * 72 + n));
                vf[2 * p][0] = r[0]; vf[2 * p][1] = r[1];
                vf[2 * p + 1][0] = r[2]; vf[2 * p + 1][1] = r[3];
            }
#pragma unroll
            for (int j = 0; j < 8; j++) {
                mma16816(O[j], ph, vf[j]);
                mma16816(O[j], pl, vf[j]);
            }
        }
        __syncthreads();  // reads of buf done before its refill next iteration
        buf ^= 1;
    }

    float inv0 = 1.f / l_[0], inv1 = 1.f / l_[1];
    int r0 = tok0 + wq + (lane >> 2);
#pragma unroll
    for (int j = 0; j < 8; j++) {
        int col = h * HDIM + j * 8 + (lane & 3) * 2;
        *(uint32_t*)(oh + (size_t)r0 * DMODEL + col) =
            pack_h2(__float2half_rn(O[j][0] * inv0), __float2half_rn(O[j][1] * inv0));
        *(uint32_t*)(oh + (size_t)(r0 + 8) * DMODEL + col) =
            pack_h2(__float2half_rn(O[j][2] * inv1), __float2half_rn(O[j][3] * inv1));
    }
}

// ---------------- gate / bucketing -------------------------------------------------
__global__ void zero_kernel() {
    if (threadIdx.x < NTILES) { g_cnt[threadIdx.x] = 0; g_fill[threadIdx.x] = 0; }
}

__global__ void gate_kernel(const float* __restrict__ n2, const float* __restrict__ gw,
                            const float* __restrict__ gb, float* __restrict__ gate_out) {
    int t = blockIdx.x;
    const float* xr = n2 + (size_t)t * DMODEL;
    float lg[NTILES] = {};
    for (int d = threadIdx.x; d < DMODEL; d += 256) {
        float v = xr[d];
#pragma unroll
        for (int e = 0; e < NTILES; e++) lg[e] += v * gw[e * DMODEL + d];
    }
#pragma unroll
    for (int o = 16; o; o >>= 1)
#pragma unroll
        for (int e = 0; e < NTILES; e++) lg[e] += __shfl_xor_sync(0xffffffffu, lg[e], o);
    __shared__ float smv[8][NTILES];
    if ((threadIdx.x & 31) == 0)
#pragma unroll
        for (int e = 0; e < NTILES; e++) smv[threadIdx.x >> 5][e] = lg[e];
    __syncthreads();
    if (threadIdx.x == 0) {
        int best = 0; float bv = -1e30f;
#pragma unroll
        for (int e = 0; e < NTILES; e++) {
            float v = gb[e];
#pragma unroll
            for (int w = 0; w < 8; w++) v += smv[w][e];
            if (v > bv) { bv = v; best = e; }
        }
        g_tile_id[t] = best;
#pragma unroll
        for (int e = 0; e < NTILES; e++) gate_out[(size_t)t * NTILES + e] = (e == best) ? 1.f : 0.f;
        atomicAdd(&g_cnt[best], 1);
    }
}

__global__ void scan_kernel() {
    if (threadIdx.x == 0) {
        int a = 0;
        for (int e = 0; e < NTILES; e++) { g_off[e] = a; a += g_cnt[e]; }
    }
}

__global__ void scatter_kernel() {
    int t = blockIdx.x * 256 + threadIdx.x;
    int e = g_tile_id[t];
    int p = atomicAdd(&g_fill[e], 1);
    g_perm[g_off[e] + p] = t;
}

// ---------------- launch ------------------------------------------------------------
extern "C" void kernel_launch(void* const* d_in, const int* in_sizes, int n_in,
                              void* d_out, int out_size) {
    const float* x      = (const float*)d_in[0];
    const float* ln1_g  = (const float*)d_in[1];
    const float* ln1_b  = (const float*)d_in[2];
    const float* qkv_w  = (const float*)d_in[3];
    const float* qkv_b  = (const float*)d_in[4];
    const float* out_w  = (const float*)d_in[5];
    const float* out_b  = (const float*)d_in[6];
    const float* ln2_g  = (const float*)d_in[7];
    const float* ln2_b  = (const float*)d_in[8];
    const float* gate_w = (const float*)d_in[9];
    const float* gate_b = (const float*)d_in[10];
    const float* up_W   = (const float*)d_in[11];
    const float* up_b   = (const float*)d_in[12];
    const float* down_W = (const float*)d_in[13];
    const float* down_b = (const float*)d_in[14];

    float* outp = (float*)d_out;
    float* gate_out = outp + (size_t)NTOK * DMODEL;

    void* p;
    cudaGetSymbolAddress(&p, g_qkv);  __half* qkvh = (__half*)p;
    cudaGetSymbolAddress(&p, g_xres); float* xres = (float*)p;
    cudaGetSymbolAddress(&p, g_n2);   float* n2   = (float*)p;
    cudaGetSymbolAddress(&p, g_n1);   __half* n1h = (__half*)p;
    cudaGetSymbolAddress(&p, g_attn); __half* ath = (__half*)p;
    cudaGetSymbolAddress(&p, g_n2x);  __half* n2h = (__half*)p;
    cudaGetSymbolAddress(&p, g_h);    __half* hh = (__half*)p;
    cudaGetSymbolAddress(&p, g_qkvw); __half* qw = (__half*)p;
    cudaGetSymbolAddress(&p, g_outw); __half* ow = (__half*)p;
    cudaGetSymbolAddress(&p, g_upw);  __half* uw = (__half*)p;
    cudaGetSymbolAddress(&p, g_dnw);  __half* dw = (__half*)p;

    const int smem_nt = 4 * STG_NT;
    const int smem_t  = 4 * STG_T;
    cudaFuncSetAttribute(gemm_cp<0, false>, cudaFuncAttributeMaxDynamicSharedMemorySize, smem_nt);
    cudaFuncSetAttribute(gemm_cp<1, false>, cudaFuncAttributeMaxDynamicSharedMemorySize, smem_nt);
    cudaFuncSetAttribute(gemm_cp<2, true>, cudaFuncAttributeMaxDynamicSharedMemorySize, smem_t);
    cudaFuncSetAttribute(gemm_cp<3, true>, cudaFuncAttributeMaxDynamicSharedMemorySize, smem_t);

    // 0) weight convert
    wconv<<<D3 * DMODEL / 1024, 256>>>(qkv_w, qw);
    wconv<<<DMODEL * DMODEL / 1024, 256>>>(out_w, ow);
    wconv<<<NTILES * DMODEL * DFF / 1024, 256>>>(up_W, uw);
    wconv<<<NTILES * DFF * DMODEL / 1024, 256>>>(down_W, dw);

    // 1) LN1 (fp16 out)
    ln_conv<false><<<NTOK, 256>>>(x, ln1_g, ln1_b, nullptr, n1h);
    // 2) QKV projection -> fp16
    gemm_cp<0, false><<<dim3(D3 / 128, NTOK / 128), 512, smem_nt>>>(
        n1h, qw, qkv_b, nullptr, nullptr, qkvh, D3, DMODEL);
    // 3) attention (fp16 in/out)
    attn_mma<<<dim3(SEQ / 64, NHEAD, NB), 128>>>(qkvh, ath);
    // 4) out projection + residual -> fp32
    gemm_cp<1, false><<<dim3(DMODEL / 128, NTOK / 128), 512, smem_nt>>>(
        ath, ow, out_b, x, xres, nullptr, DMODEL, DMODEL);
    // 5) LN2 (fp32 + fp16)
    ln_conv<true><<<NTOK, 256>>>(xres, ln2_g, ln2_b, n2, n2h);
    // 6) gate + bucketing
    zero_kernel<<<1, 32>>>();
    gate_kernel<<<NTOK, 256>>>(n2, gate_w, gate_b, gate_out);
    scan_kernel<<<1, 32>>>();
    scatter_kernel<<<NTOK / 256, 256>>>();
    // 7) FFN
    gemm_cp<2, true><<<dim3(DFF / 128, NTOK / 128, NTILES), 512, smem_t>>>(
        n2h, uw, up_b, nullptr, nullptr, hh, DFF, DMODEL);
    gemm_cp<3, true><<<dim3(DMODEL / 128, NTOK / 128, NTILES), 512, smem_t>>>(
        hh, dw, down_b, xres, outp, nullptr, DMODEL, DFF);
}